// round 7
// baseline (speedup 1.0000x reference)
#include <cuda_runtime.h>
#include <cstdint>
#include <cstddef>

#define N_TOKENS 8192
#define HDIM     1024
#define NHEADS   16
#define SLOTS    16
#define SD       32
#define HD       64
#define FULLMASK 0xffffffffu

typedef unsigned long long u64;

__device__ float4 g_act4[N_TOKENS * NHEADS];
__device__ float  g_WaT[48 * HDIM];                      // WaT[col][k]
__device__ float  g_part[4 * N_TOKENS * 48];             // k-split partials
__device__ float4 g_kv4[(size_t)N_TOKENS * NHEADS * 8];  // kv [tok][head][32]
__device__ float4 g_mem4[(size_t)N_TOKENS * NHEADS * 8]; // mem [tok][head][32]

// ---------------------- helpers ----------------------
__device__ __forceinline__ u64 pack2(float x, float y) {
    u64 r; asm("mov.b64 %0,{%1,%2};" : "=l"(r) : "f"(x), "f"(y)); return r;
}
__device__ __forceinline__ void fma2(u64& d, u64 a, u64 b) {
    asm("fma.rn.f32x2 %0,%1,%2,%0;" : "+l"(d) : "l"(a), "l"(b));
}
__device__ __forceinline__ float2 unpack2(u64 v) {
    float2 r; asm("mov.b64 {%0,%1},%2;" : "=f"(r.x), "=f"(r.y) : "l"(v)); return r;
}
__device__ __forceinline__ float4 f4zero() { return make_float4(0.f, 0.f, 0.f, 0.f); }
__device__ __forceinline__ float4 f4fma(float a, float4 b, float4 c) {
    return make_float4(fmaf(a, b.x, c.x), fmaf(a, b.y, c.y),
                       fmaf(a, b.z, c.z), fmaf(a, b.w, c.w));
}
__device__ __forceinline__ float4 f4add(float4 a, float4 b) {
    return make_float4(a.x + b.x, a.y + b.y, a.z + b.z, a.w + b.w);
}
__device__ __forceinline__ float dot4(float4 a, float4 b) {
    return fmaf(a.x, b.x, fmaf(a.y, b.y, fmaf(a.z, b.z, a.w * b.w)));
}
__device__ __forceinline__ float4 f4shflxor(float4 v, int m) {
    return make_float4(__shfl_xor_sync(FULLMASK, v.x, m),
                       __shfl_xor_sync(FULLMASK, v.y, m),
                       __shfl_xor_sync(FULLMASK, v.z, m),
                       __shfl_xor_sync(FULLMASK, v.w, m));
}

// ---------------------------------------------------------------------------
// Kernel 0: transpose Wa [1024][48] -> g_WaT [48][1024]
// ---------------------------------------------------------------------------
__global__ __launch_bounds__(256) void k_waT(const float* __restrict__ Wa)
{
    const int col = blockIdx.x >> 2;
    const int k   = (blockIdx.x & 3) * 256 + threadIdx.x;
    g_WaT[col * HDIM + k] = Wa[(size_t)k * 48 + col];
}

// ---------------------------------------------------------------------------
// Kernel 1: FUSED action-logit partials + kv projection.
// Block = 64 tok x k-chunk kc (256 floats = heads 4kc..4kc+3).
// Each sub-chunk of 64 k IS the hidden slice of head 4kc+sub, so kv for that
// head is accumulated inside the same inner loop reusing the sA loads.
// Thread: ty=tid>>3 (2 tokens), tx=tid&7 (6 action cols; kv sd-pairs 2tx,2tx+1).
// ---------------------------------------------------------------------------
__global__ __launch_bounds__(256) void k_act_kv(
    const float* __restrict__ hidden,
    const float* __restrict__ Wd,
    const float* __restrict__ bd)
{
    __shared__ __align__(16) float sA[64][68];    // 17.4 KB
    __shared__ __align__(16) float sWT[48][68];   // 13.1 KB
    __shared__ __align__(16) u64   sWd2[64 * 16]; // 8 KB  [d][sd-pair]

    const int tid  = threadIdx.x;
    const int ty   = tid >> 3;
    const int tx   = tid & 7;
    const int tile = blockIdx.x >> 2;
    const int kc   = blockIdx.x & 3;
    const int tok0 = tile * 64;
    const float4* hid4 = (const float4*)hidden;
    const float4* waT4 = (const float4*)g_WaT;

    // Wd fill (contiguous, once)
    ((float4*)sWd2)[tid]       = ((const float4*)Wd)[tid];
    ((float4*)sWd2)[tid + 256] = ((const float4*)Wd)[tid + 256];

    // kv biases
    const u64* bd2 = (const u64*)bd;
    const u64 b0 = __ldg(&bd2[tx * 2]);
    const u64 b1 = __ldg(&bd2[tx * 2 + 1]);

    u64 acc[2][6];
#pragma unroll
    for (int t = 0; t < 2; t++)
#pragma unroll
        for (int j = 0; j < 6; j++) acc[t][j] = 0ull;

#pragma unroll
    for (int sub = 0; sub < 4; sub++) {
        const int k4 = kc * 64 + sub * 16;   // f4 base index in k
#pragma unroll
        for (int idx = tid; idx < 1024; idx += 256) {
            int r = idx >> 4, c4 = idx & 15;
            *(float4*)&sA[r][c4 * 4] = hid4[(size_t)(tok0 + r) * 256 + k4 + c4];
        }
#pragma unroll
        for (int idx = tid; idx < 768; idx += 256) {
            int r = idx >> 4, c4 = idx & 15;
            *(float4*)&sWT[r][c4 * 4] = waT4[(size_t)r * 256 + k4 + c4];
        }
        __syncthreads();

        u64 kacc[2][2];
        kacc[0][0] = b0; kacc[0][1] = b1;
        kacc[1][0] = b0; kacc[1][1] = b1;

#pragma unroll 8
        for (int k2 = 0; k2 < 32; k2++) {
            u64 a0 = *(const u64*)&sA[ty * 2 + 0][k2 * 2];
            u64 a1 = *(const u64*)&sA[ty * 2 + 1][k2 * 2];
            // action partials
#pragma unroll
            for (int j = 0; j < 6; j++) {
                u64 w = *(const u64*)&sWT[tx * 6 + j][k2 * 2];
                fma2(acc[0][j], a0, w);
                fma2(acc[1][j], a1, w);
            }
            // kv for head = 4kc+sub, local d = 2k2, 2k2+1
            const int d0 = k2 * 2;
            ulonglong2 wd0 = *(const ulonglong2*)&sWd2[d0 * 16 + tx * 2];
            ulonglong2 wd1 = *(const ulonglong2*)&sWd2[(d0 + 1) * 16 + tx * 2];
            {
                float2 av = unpack2(a0);
                u64 hx = pack2(av.x, av.x), hy = pack2(av.y, av.y);
                fma2(kacc[0][0], hx, wd0.x); fma2(kacc[0][1], hx, wd0.y);
                fma2(kacc[0][0], hy, wd1.x); fma2(kacc[0][1], hy, wd1.y);
            }
            {
                float2 av = unpack2(a1);
                u64 hx = pack2(av.x, av.x), hy = pack2(av.y, av.y);
                fma2(kacc[1][0], hx, wd0.x); fma2(kacc[1][1], hx, wd0.y);
                fma2(kacc[1][0], hy, wd1.x); fma2(kacc[1][1], hy, wd1.y);
            }
        }
        __syncthreads();

        // store kv for this head
        const int head = kc * 4 + sub;
#pragma unroll
        for (int t = 0; t < 2; t++) {
            float2 p0 = unpack2(kacc[t][0]);
            float2 p1 = unpack2(kacc[t][1]);
            __stcs(&g_kv4[((size_t)(tok0 + ty * 2 + t) * NHEADS + head) * 8 + tx],
                   make_float4(p0.x, p0.y, p1.x, p1.y));
        }
    }

    // store action partials (accumulated over all 4 subs = this 256-k chunk)
#pragma unroll
    for (int t = 0; t < 2; t++) {
        const size_t base = ((size_t)kc * N_TOKENS + tok0 + ty * 2 + t) * 48 + tx * 6;
#pragma unroll
        for (int j2 = 0; j2 < 3; j2++) {
            float2 pa = unpack2(acc[t][j2 * 2]);
            float2 pb = unpack2(acc[t][j2 * 2 + 1]);
            *(float2*)&g_part[base + j2 * 2] = make_float2(pa.x + pa.y, pb.x + pb.y);
        }
    }
}

// ---------------------------------------------------------------------------
// Kernel 1b: reduce partials + softmax_3 -> g_act4.
// ---------------------------------------------------------------------------
__global__ __launch_bounds__(256) void k_act_reduce(const float* __restrict__ ba)
{
    const int tid   = threadIdx.x;
    const int head  = tid & 15;
    const int token = blockIdx.x * 16 + (tid >> 4);

    float l[3];
#pragma unroll
    for (int j = 0; j < 3; j++) {
        const size_t col = (size_t)token * 48 + head * 3 + j;
        float s = g_part[col]
                + g_part[(size_t)N_TOKENS * 48 + col]
                + g_part[(size_t)2 * N_TOKENS * 48 + col]
                + g_part[(size_t)3 * N_TOKENS * 48 + col];
        l[j] = (s + __ldg(&ba[head * 3 + j])) * 0.125f;
    }
    float mx = fmaxf(l[0], fmaxf(l[1], l[2]));
    float e0 = __expf(l[0] - mx);
    float e1 = __expf(l[1] - mx);
    float e2 = __expf(l[2] - mx);
    float inv = 1.f / (e0 + e1 + e2);
    g_act4[(size_t)token * NHEADS + head] = make_float4(e0 * inv, e1 * inv, e2 * inv, 0.f);
}

// ---------------------------------------------------------------------------
// Kernel 3: stack update + gate softmax + mem. Warp = (token, head).
// ---------------------------------------------------------------------------
__global__ __launch_bounds__(256, 3) void k_stack(
    const float* __restrict__ stack,
    const float* __restrict__ mask,
    const float* __restrict__ Wg,
    const float* __restrict__ bg,
    float* __restrict__ new_stack,
    float* __restrict__ new_mask)
{
    const int tid  = threadIdx.x;
    const int wl   = tid >> 5;
    const int lane = tid & 31;
    const int g    = lane >> 3;
    const int c    = lane & 7;

    const size_t th = (size_t)blockIdx.x * 8 + wl;
    const float4* stk4 = (const float4*)stack + th * 128;

    float4 st[4];
#pragma unroll
    for (int i = 0; i < 4; i++) st[i] = __ldcs(&stk4[i * 32 + lane]);

    const float4 kv4 = __ldg(&g_kv4[th * 8 + c]);
    const float4 act = __ldg(&g_act4[th]);
    const float a_push = act.x, a_pop = act.y, a_noop = act.z;
    const float4 wg4 = __ldg(&((const float4*)Wg)[c]);

    float q[4];
#pragma unroll
    for (int i = 0; i < 4; i++) {
        q[i] = dot4(st[i], wg4);
        q[i] += __shfl_xor_sync(FULLMASK, q[i], 1);
        q[i] += __shfl_xor_sync(FULLMASK, q[i], 2);
        q[i] += __shfl_xor_sync(FULLMASK, q[i], 4);
    }
    float qk = dot4(kv4, wg4);
    qk += __shfl_xor_sync(FULLMASK, qk, 1);
    qk += __shfl_xor_sync(FULLMASK, qk, 2);
    qk += __shfl_xor_sync(FULLMASK, qk, 4);

    float qn[4], qp[4];
#pragma unroll
    for (int i = 0; i < 4; i++) {
        float sn = (g == 0) ? ((i < 3) ? q[i + 1] : 0.f) : q[i];
        qn[i] = __shfl_sync(FULLMASK, sn, (lane + 8) & 31);
        float sp = (g == 3) ? ((i > 0) ? q[i - 1] : 0.f) : q[i];
        qp[i] = __shfl_sync(FULLMASK, sp, (lane + 24) & 31);
    }
    if (g == 0) qp[0] = qk;

    const float bgv = __ldg(&bg[0]);
    const float* mk = mask + th * SLOTS;
    float nm[4], e[4];
    float mx = -3.4e38f;
#pragma unroll
    for (int i = 0; i < 4; i++) {
        const int slot = i * 4 + g;
        float m  = __ldcs(&mk[slot]);
        float mn = (slot < 15) ? __ldcs(&mk[slot + 1]) : 0.f;
        float mp = (slot > 0)  ? __ldcs(&mk[slot - 1]) : 1.f;
        nm[i] = fmaf(a_push, mp, fmaf(a_pop, mn, a_noop * m));
        float sc = fmaf(a_push, qp[i], fmaf(a_pop, qn[i], a_noop * q[i])) + bgv;
        sc += (1.f - nm[i]) * (-1e9f);
        e[i] = sc;
        mx = fmaxf(mx, sc);
    }
    mx = fmaxf(mx, __shfl_xor_sync(FULLMASK, mx, 8));
    mx = fmaxf(mx, __shfl_xor_sync(FULLMASK, mx, 16));
    float ssum = 0.f;
#pragma unroll
    for (int i = 0; i < 4; i++) { e[i] = __expf(e[i] - mx); ssum += e[i]; }
    ssum += __shfl_xor_sync(FULLMASK, ssum, 8);
    ssum += __shfl_xor_sync(FULLMASK, ssum, 16);
    const float ginv = 1.f / ssum;

    if (c == 0) {
#pragma unroll
        for (int i = 0; i < 4; i++)
            __stcs(&new_mask[th * SLOTS + i * 4 + g], nm[i]);
    }

    float4* nst4 = (float4*)new_stack + th * 128;
    float4 acc = f4zero();
#pragma unroll
    for (int i = 0; i < 4; i++) {
        const int slot = i * 4 + g;
        float4 nx = (slot < 15) ? __ldcs(&stk4[i * 32 + lane + 8]) : f4zero();
        float4 pv = (slot > 0)  ? __ldcs(&stk4[i * 32 + lane - 8]) : kv4;
        float4 ns;
        ns.x = fmaf(a_push, pv.x, fmaf(a_pop, nx.x, a_noop * st[i].x));
        ns.y = fmaf(a_push, pv.y, fmaf(a_pop, nx.y, a_noop * st[i].y));
        ns.z = fmaf(a_push, pv.z, fmaf(a_pop, nx.z, a_noop * st[i].z));
        ns.w = fmaf(a_push, pv.w, fmaf(a_pop, nx.w, a_noop * st[i].w));
        __stcs(&nst4[i * 32 + lane], ns);
        acc = f4fma(e[i] * ginv, ns, acc);
    }
    acc = f4add(acc, f4shflxor(acc, 8));
    acc = f4add(acc, f4shflxor(acc, 16));
    if (g == 0)
        g_mem4[th * 8 + c] = acc;
}

// ---------------------------------------------------------------------------
// Kernel 4: out = (mem @ Wu + bu)*rw + hidden. Block = 128 tok x 1 head.
// tg = tid>>3 (4 tokens), dg = tid&7 (4 d-pairs). Wu in natural u64 layout
// [sd][pair] -> 2 LDS.128 per sd; mem tile transposed [sd][tok] XOR-swizzled.
// ---------------------------------------------------------------------------
__global__ __launch_bounds__(256) void k_out(
    const float* __restrict__ hidden,
    const float* __restrict__ Wu,
    const float* __restrict__ bu,
    const float* __restrict__ res_w,
    float* __restrict__ out)
{
    __shared__ __align__(16) float sMT[32 * 128];   // 16 KB
    __shared__ __align__(16) u64   sWu2[32 * 32];   // 8 KB [sd][pair]

    const int tid  = threadIdx.x;
    const int head = blockIdx.x & 15;
    const int tok0 = (blockIdx.x >> 4) * 128;
    const int dg   = tid & 7;
    const int tg   = tid >> 3;

    ((float4*)sWu2)[tid]       = ((const float4*)Wu)[tid];
    ((float4*)sWu2)[tid + 256] = ((const float4*)Wu)[tid + 256];

#pragma unroll
    for (int k = 0; k < 4; k++) {
        int idx = k * 256 + tid;
        int tok = idx >> 3, j2 = idx & 7;
        float4 v = g_mem4[((size_t)(tok0 + tok) * NHEADS + head) * 8 + j2];
        int s0 = j2 * 4;
        const int tq = tok >> 2, tr = tok & 3;
        sMT[(s0 + 0) * 128 + (((tq ^ (s0 + 0)) & 31) << 2) + tr] = v.x;
        sMT[(s0 + 1) * 128 + (((tq ^ (s0 + 1)) & 31) << 2) + tr] = v.y;
        sMT[(s0 + 2) * 128 + (((tq ^ (s0 + 2)) & 31) << 2) + tr] = v.z;
        sMT[(s0 + 3) * 128 + (((tq ^ (s0 + 3)) & 31) << 2) + tr] = v.w;
    }
    __syncthreads();

    u64 acc[4][4];
    {
        const u64* bu2 = (const u64*)bu;
#pragma unroll
        for (int j = 0; j < 4; j++) {
            u64 b = __ldg(&bu2[dg * 4 + j]);
            acc[0][j] = b; acc[1][j] = b; acc[2][j] = b; acc[3][j] = b;
        }
    }

#pragma unroll 8
    for (int sd = 0; sd < SD; sd++) {
        float4 a4 = *(const float4*)&sMT[sd * 128 + (((tg ^ sd) & 31) << 2)];
        ulonglong2 w01 = *(const ulonglong2*)&sWu2[sd * 32 + dg * 4];
        ulonglong2 w23 = *(const ulonglong2*)&sWu2[sd * 32 + dg * 4 + 2];
        u64 h0 = pack2(a4.x, a4.x), h1 = pack2(a4.y, a4.y);
        u64 h2 = pack2(a4.z, a4.z), h3 = pack2(a4.w, a4.w);
        fma2(acc[0][0], h0, w01.x); fma2(acc[0][1], h0, w01.y);
        fma2(acc[0][2], h0, w23.x); fma2(acc[0][3], h0, w23.y);
        fma2(acc[1][0], h1, w01.x); fma2(acc[1][1], h1, w01.y);
        fma2(acc[1][2], h1, w23.x); fma2(acc[1][3], h1, w23.y);
        fma2(acc[2][0], h2, w01.x); fma2(acc[2][1], h2, w01.y);
        fma2(acc[2][2], h2, w23.x); fma2(acc[2][3], h2, w23.y);
        fma2(acc[3][0], h3, w01.x); fma2(acc[3][1], h3, w01.y);
        fma2(acc[3][2], h3, w23.x); fma2(acc[3][3], h3, w23.y);
    }

    const float rw = __ldg(&res_w[0]);
#pragma unroll
    for (int t = 0; t < 4; t++) {
        const int token = tok0 + tg * 4 + t;
        const size_t base = (size_t)token * 256 + head * 16 + dg * 2;
        const float4* hid4 = (const float4*)hidden + base;
        float4* out4 = (float4*)out + base;
        float2 aa = unpack2(acc[t][0]);
        float2 ab = unpack2(acc[t][1]);
        float2 ac = unpack2(acc[t][2]);
        float2 ad = unpack2(acc[t][3]);
        float4 h0 = __ldcs(&hid4[0]);
        float4 h1 = __ldcs(&hid4[1]);
        float4 o0, o1;
        o0.x = fmaf(aa.x, rw, h0.x); o0.y = fmaf(aa.y, rw, h0.y);
        o0.z = fmaf(ab.x, rw, h0.z); o0.w = fmaf(ab.y, rw, h0.w);
        o1.x = fmaf(ac.x, rw, h1.x); o1.y = fmaf(ac.y, rw, h1.y);
        o1.z = fmaf(ad.x, rw, h1.z); o1.w = fmaf(ad.y, rw, h1.w);
        __stcs(&out4[0], o0);
        __stcs(&out4[1], o1);
    }
}

// ---------------------------------------------------------------------------
extern "C" void kernel_launch(void* const* d_in, const int* in_sizes, int n_in,
                              void* d_out, int out_size)
{
    const float* hidden = (const float*)d_in[0];
    const float* stack  = (const float*)d_in[1];
    const float* mask   = (const float*)d_in[2];
    const float* Wa     = (const float*)d_in[3];
    const float* ba     = (const float*)d_in[4];
    const float* Wd     = (const float*)d_in[5];
    const float* bd     = (const float*)d_in[6];
    const float* Wu     = (const float*)d_in[7];
    const float* bu     = (const float*)d_in[8];
    const float* Wg     = (const float*)d_in[9];
    const float* bg     = (const float*)d_in[10];
    const float* res_w  = (const float*)d_in[11];

    float* out       = (float*)d_out;
    float* new_stack = out + (size_t)N_TOKENS * HDIM;
    float* new_mask  = new_stack + (size_t)N_TOKENS * NHEADS * SLOTS * SD;

    (void)in_sizes; (void)n_in; (void)out_size;

    k_waT<<<192, 256>>>(Wa);
    k_act_kv<<<(N_TOKENS / 64) * 4, 256>>>(hidden, Wd, bd);
    k_act_reduce<<<N_TOKENS / 16, 256>>>(ba);
    k_stack<<<N_TOKENS * NHEADS / 8, 256>>>(stack, mask, Wg, bg,
                                            new_stack, new_mask);
    k_out<<<(N_TOKENS / 128) * NHEADS, 256>>>(hidden, Wu, bu, res_w, out);
}

// round 8
// speedup vs baseline: 1.1369x; 1.1369x over previous
#include <cuda_runtime.h>
#include <cstdint>
#include <cstddef>

#define N_TOKENS 8192
#define HDIM     1024
#define NHEADS   16
#define SLOTS    16
#define SD       32
#define HD       64
#define FULLMASK 0xffffffffu

typedef unsigned long long u64;

__device__ float4 g_act4[N_TOKENS * NHEADS];
__device__ float  g_WaT[48 * HDIM];                      // WaT[col][k]
__device__ float  g_part[4 * N_TOKENS * 48];             // k-split partials
__device__ float4 g_kv4[(size_t)N_TOKENS * NHEADS * 8];  // kv [tok][head][32]
__device__ float4 g_mem4[(size_t)N_TOKENS * NHEADS * 8]; // mem [tok][head][32]

// ---------------------- helpers ----------------------
__device__ __forceinline__ u64 pack2(float x, float y) {
    u64 r; asm("mov.b64 %0,{%1,%2};" : "=l"(r) : "f"(x), "f"(y)); return r;
}
__device__ __forceinline__ void fma2(u64& d, u64 a, u64 b) {
    asm("fma.rn.f32x2 %0,%1,%2,%0;" : "+l"(d) : "l"(a), "l"(b));
}
__device__ __forceinline__ float2 unpack2(u64 v) {
    float2 r; asm("mov.b64 {%0,%1},%2;" : "=f"(r.x), "=f"(r.y) : "l"(v)); return r;
}
__device__ __forceinline__ float4 f4zero() { return make_float4(0.f, 0.f, 0.f, 0.f); }
__device__ __forceinline__ float4 f4fma(float a, float4 b, float4 c) {
    return make_float4(fmaf(a, b.x, c.x), fmaf(a, b.y, c.y),
                       fmaf(a, b.z, c.z), fmaf(a, b.w, c.w));
}
__device__ __forceinline__ float4 f4add(float4 a, float4 b) {
    return make_float4(a.x + b.x, a.y + b.y, a.z + b.z, a.w + b.w);
}
__device__ __forceinline__ float dot4(float4 a, float4 b) {
    return fmaf(a.x, b.x, fmaf(a.y, b.y, fmaf(a.z, b.z, a.w * b.w)));
}
__device__ __forceinline__ float4 f4shflxor(float4 v, int m) {
    return make_float4(__shfl_xor_sync(FULLMASK, v.x, m),
                       __shfl_xor_sync(FULLMASK, v.y, m),
                       __shfl_xor_sync(FULLMASK, v.z, m),
                       __shfl_xor_sync(FULLMASK, v.w, m));
}

// ---------------------------------------------------------------------------
// Kernel 0: transpose Wa [1024][48] -> g_WaT [48][1024]
// ---------------------------------------------------------------------------
__global__ __launch_bounds__(256) void k_waT(const float* __restrict__ Wa)
{
    const int col = blockIdx.x >> 2;
    const int k   = (blockIdx.x & 3) * 256 + threadIdx.x;
    g_WaT[col * HDIM + k] = Wa[(size_t)k * 48 + col];
}

// ---------------------------------------------------------------------------
// Kernel 1a: partial logits GEMM. Block = 128 tok x 48 col x 256-k chunk.
// ---------------------------------------------------------------------------
__global__ __launch_bounds__(256) void k_actions_part(
    const float* __restrict__ hidden)
{
    __shared__ __align__(16) float sA[128][68];
    __shared__ __align__(16) float sWT[48][68];

    const int tid  = threadIdx.x;
    const int ty   = tid >> 3;
    const int tx   = tid & 7;
    const int tile = blockIdx.x >> 2;
    const int kc   = blockIdx.x & 3;
    const int tok0 = tile * 128;
    const float4* hid4 = (const float4*)hidden;
    const float4* waT4 = (const float4*)g_WaT;

    u64 acc[4][6];
#pragma unroll
    for (int t = 0; t < 4; t++)
#pragma unroll
        for (int j = 0; j < 6; j++) acc[t][j] = 0ull;

#pragma unroll
    for (int sub = 0; sub < 4; sub++) {
        const int k4 = kc * 64 + sub * 16;
#pragma unroll
        for (int idx = tid; idx < 2048; idx += 256) {
            int r = idx >> 4, c4 = idx & 15;
            *(float4*)&sA[r][c4 * 4] = hid4[(size_t)(tok0 + r) * 256 + k4 + c4];
        }
#pragma unroll
        for (int idx = tid; idx < 768; idx += 256) {
            int r = idx >> 4, c4 = idx & 15;
            *(float4*)&sWT[r][c4 * 4] = waT4[(size_t)r * 256 + k4 + c4];
        }
        __syncthreads();

#pragma unroll 8
        for (int k2 = 0; k2 < 32; k2++) {
            u64 a[4];
#pragma unroll
            for (int t = 0; t < 4; t++)
                a[t] = *(const u64*)&sA[ty * 4 + t][k2 * 2];
#pragma unroll
            for (int j = 0; j < 6; j++) {
                u64 w = *(const u64*)&sWT[tx * 6 + j][k2 * 2];
                fma2(acc[0][j], a[0], w);
                fma2(acc[1][j], a[1], w);
                fma2(acc[2][j], a[2], w);
                fma2(acc[3][j], a[3], w);
            }
        }
        __syncthreads();
    }

#pragma unroll
    for (int t = 0; t < 4; t++) {
        const size_t base = ((size_t)kc * N_TOKENS + tok0 + ty * 4 + t) * 48 + tx * 6;
#pragma unroll
        for (int j2 = 0; j2 < 3; j2++) {
            float2 pa = unpack2(acc[t][j2 * 2]);
            float2 pb = unpack2(acc[t][j2 * 2 + 1]);
            *(float2*)&g_part[base + j2 * 2] = make_float2(pa.x + pa.y, pb.x + pb.y);
        }
    }
}

// ---------------------------------------------------------------------------
// Kernel 1b: reduce partials + softmax_3 -> g_act4.
// ---------------------------------------------------------------------------
__global__ __launch_bounds__(256) void k_act_reduce(const float* __restrict__ ba)
{
    const int tid   = threadIdx.x;
    const int head  = tid & 15;
    const int token = blockIdx.x * 16 + (tid >> 4);

    float l[3];
#pragma unroll
    for (int j = 0; j < 3; j++) {
        const size_t col = (size_t)token * 48 + head * 3 + j;
        float s = g_part[col]
                + g_part[(size_t)N_TOKENS * 48 + col]
                + g_part[(size_t)2 * N_TOKENS * 48 + col]
                + g_part[(size_t)3 * N_TOKENS * 48 + col];
        l[j] = (s + __ldg(&ba[head * 3 + j])) * 0.125f;
    }
    float mx = fmaxf(l[0], fmaxf(l[1], l[2]));
    float e0 = __expf(l[0] - mx);
    float e1 = __expf(l[1] - mx);
    float e2 = __expf(l[2] - mx);
    float inv = 1.f / (e0 + e1 + e2);
    g_act4[(size_t)token * NHEADS + head] = make_float4(e0 * inv, e1 * inv, e2 * inv, 0.f);
}

// ---------------------------------------------------------------------------
// Kernel 2: kv = hidden-slice @ Wd + bd. Block = 128 tok x 1 head, 256 thr.
// ---------------------------------------------------------------------------
__global__ __launch_bounds__(256) void k_kv(
    const float* __restrict__ hidden,
    const float* __restrict__ Wd,
    const float* __restrict__ bd)
{
    __shared__ __align__(16) float sAT[64 * 128];   // 32 KB
    __shared__ __align__(16) u64   sWd2[64 * 16];   // 8 KB [d][pair]

    const int tid  = threadIdx.x;
    const int head = blockIdx.x & 15;
    const int tok0 = (blockIdx.x >> 4) * 128;
    const int jg   = tid & 7;
    const int tg   = tid >> 3;

    ((float4*)sWd2)[tid]       = ((const float4*)Wd)[tid];
    ((float4*)sWd2)[tid + 256] = ((const float4*)Wd)[tid + 256];

    const float4* hid4 = (const float4*)hidden;
#pragma unroll
    for (int k = 0; k < 8; k++) {
        int idx = k * 256 + tid;
        int tok = idx >> 4, c4 = idx & 15;
        float4 v = __ldcs(&hid4[(size_t)(tok0 + tok) * 256 + head * 16 + c4]);
        int d0 = c4 * 4;
        const int tq = tok >> 2, tr = tok & 3;
        sAT[(d0 + 0) * 128 + ((tq ^ ((d0 + 0) & 31)) << 2) + tr] = v.x;
        sAT[(d0 + 1) * 128 + ((tq ^ ((d0 + 1) & 31)) << 2) + tr] = v.y;
        sAT[(d0 + 2) * 128 + ((tq ^ ((d0 + 2) & 31)) << 2) + tr] = v.z;
        sAT[(d0 + 3) * 128 + ((tq ^ ((d0 + 3) & 31)) << 2) + tr] = v.w;
    }
    __syncthreads();

    u64 acc[4][2];
    {
        const u64* bd2 = (const u64*)bd;
        u64 b0 = __ldg(&bd2[jg * 2]);
        u64 b1 = __ldg(&bd2[jg * 2 + 1]);
#pragma unroll
        for (int t = 0; t < 4; t++) { acc[t][0] = b0; acc[t][1] = b1; }
    }

#pragma unroll 16
    for (int d = 0; d < HD; d++) {
        float4 a4 = *(const float4*)&sAT[d * 128 + ((tg ^ (d & 31)) << 2)];
        const u64* wp = &sWd2[d * 16 + jg * 2];
        u64 w0 = wp[0], w1 = wp[1];
        u64 h0 = pack2(a4.x, a4.x), h1 = pack2(a4.y, a4.y);
        u64 h2 = pack2(a4.z, a4.z), h3 = pack2(a4.w, a4.w);
        fma2(acc[0][0], h0, w0); fma2(acc[0][1], h0, w1);
        fma2(acc[1][0], h1, w0); fma2(acc[1][1], h1, w1);
        fma2(acc[2][0], h2, w0); fma2(acc[2][1], h2, w1);
        fma2(acc[3][0], h3, w0); fma2(acc[3][1], h3, w1);
    }

    float4* kvout = g_kv4 + ((size_t)(tok0 + tg * 4) * NHEADS + head) * 8 + jg;
#pragma unroll
    for (int t = 0; t < 4; t++) {
        float2 lo = unpack2(acc[t][0]);
        float2 hi = unpack2(acc[t][1]);
        kvout[t * 128] = make_float4(lo.x, lo.y, hi.x, hi.y);
    }
}

// ---------------------------------------------------------------------------
// Kernel 3: stack update + gate softmax + mem. Warp = (token, head).
// Masks via send-rotation shuffles (4 LDG instead of 12); fused score loop
// to minimize live registers.
// ---------------------------------------------------------------------------
__global__ __launch_bounds__(256, 4) void k_stack(
    const float* __restrict__ stack,
    const float* __restrict__ mask,
    const float* __restrict__ Wg,
    const float* __restrict__ bg,
    float* __restrict__ new_stack,
    float* __restrict__ new_mask)
{
    const int tid  = threadIdx.x;
    const int wl   = tid >> 5;
    const int lane = tid & 31;
    const int g    = lane >> 3;
    const int c    = lane & 7;

    const size_t th = (size_t)blockIdx.x * 8 + wl;
    const float4* stk4 = (const float4*)stack + th * 128;

    float4 st[4];
#pragma unroll
    for (int i = 0; i < 4; i++) st[i] = __ldcs(&stk4[i * 32 + lane]);

    const float4 kv4 = __ldg(&g_kv4[th * 8 + c]);
    const float4 act = __ldg(&g_act4[th]);
    const float a_push = act.x, a_pop = act.y, a_noop = act.z;
    const float4 wg4 = __ldg(&((const float4*)Wg)[c]);

    // q[s] = Wg . stack[s]  (reduce over c)
    float q[4];
#pragma unroll
    for (int i = 0; i < 4; i++) {
        q[i] = dot4(st[i], wg4);
        q[i] += __shfl_xor_sync(FULLMASK, q[i], 1);
        q[i] += __shfl_xor_sync(FULLMASK, q[i], 2);
        q[i] += __shfl_xor_sync(FULLMASK, q[i], 4);
    }
    float qk = dot4(kv4, wg4);
    qk += __shfl_xor_sync(FULLMASK, qk, 1);
    qk += __shfl_xor_sync(FULLMASK, qk, 2);
    qk += __shfl_xor_sync(FULLMASK, qk, 4);

    // masks: one LDG per owned slot; neighbors via rotation shuffles
    const float* mk = mask + th * SLOTS;
    float m[4];
#pragma unroll
    for (int i = 0; i < 4; i++) m[i] = __ldcs(&mk[i * 4 + g]);

    const float bgv = __ldg(&bg[0]);
    float e[4];
    float mx = -3.4e38f;
#pragma unroll
    for (int i = 0; i < 4; i++) {
        // next neighbors (slot+1) from lane+8 (g+1 ring)
        float sq = (g == 0) ? ((i < 3) ? q[i + 1] : 0.f) : q[i];
        float sm = (g == 0) ? ((i < 3) ? m[i + 1] : 0.f) : m[i];
        float qn = __shfl_sync(FULLMASK, sq, (lane + 8) & 31);
        float mn = __shfl_sync(FULLMASK, sm, (lane + 8) & 31);
        // prev neighbors (slot-1) from lane+24 (g-1 ring)
        float pq = (g == 3) ? ((i > 0) ? q[i - 1] : 0.f) : q[i];
        float pm = (g == 3) ? ((i > 0) ? m[i - 1] : 1.f) : m[i];
        float qp = __shfl_sync(FULLMASK, pq, (lane + 24) & 31);
        float mp = __shfl_sync(FULLMASK, pm, (lane + 24) & 31);
        if (g == 0 && i == 0) { qp = qk; mp = 1.f; }

        float nm = fmaf(a_push, mp, fmaf(a_pop, mn, a_noop * m[i]));
        if (c == 0)
            __stcs(&new_mask[th * SLOTS + i * 4 + g], nm);
        float sc = fmaf(a_push, qp, fmaf(a_pop, qn, a_noop * q[i])) + bgv;
        sc += (1.f - nm) * (-1e9f);
        e[i] = sc;
        mx = fmaxf(mx, sc);
    }
    mx = fmaxf(mx, __shfl_xor_sync(FULLMASK, mx, 8));
    mx = fmaxf(mx, __shfl_xor_sync(FULLMASK, mx, 16));
    float ssum = 0.f;
#pragma unroll
    for (int i = 0; i < 4; i++) { e[i] = __expf(e[i] - mx); ssum += e[i]; }
    ssum += __shfl_xor_sync(FULLMASK, ssum, 8);
    ssum += __shfl_xor_sync(FULLMASK, ssum, 16);
    const float ginv = 1.f / ssum;

    float4* nst4 = (float4*)new_stack + th * 128;
    float4 acc = f4zero();
#pragma unroll
    for (int i = 0; i < 4; i++) {
        const int slot = i * 4 + g;
        float4 nx = (slot < 15) ? __ldcs(&stk4[i * 32 + lane + 8]) : f4zero();
        float4 pv = (slot > 0)  ? __ldcs(&stk4[i * 32 + lane - 8]) : kv4;
        float4 ns;
        ns.x = fmaf(a_push, pv.x, fmaf(a_pop, nx.x, a_noop * st[i].x));
        ns.y = fmaf(a_push, pv.y, fmaf(a_pop, nx.y, a_noop * st[i].y));
        ns.z = fmaf(a_push, pv.z, fmaf(a_pop, nx.z, a_noop * st[i].z));
        ns.w = fmaf(a_push, pv.w, fmaf(a_pop, nx.w, a_noop * st[i].w));
        __stcs(&nst4[i * 32 + lane], ns);
        acc = f4fma(e[i] * ginv, ns, acc);
    }
    acc = f4add(acc, f4shflxor(acc, 8));
    acc = f4add(acc, f4shflxor(acc, 16));
    if (g == 0)
        g_mem4[th * 8 + c] = acc;
}

// ---------------------------------------------------------------------------
// Kernel 4: out = (mem @ Wu + bu)*rw + hidden. Block = 128 tok x 1 head.
// mem tile stored UNtransposed as padded f4 rows [tok][9] (no scalar scatter);
// Wu in natural contiguous u64 layout [sd][pair].
// tg = tid>>3 (4 tokens), dg = tid&7 (4 d-pairs).
// ---------------------------------------------------------------------------
__global__ __launch_bounds__(256) void k_out(
    const float* __restrict__ hidden,
    const float* __restrict__ Wu,
    const float* __restrict__ bu,
    const float* __restrict__ res_w,
    float* __restrict__ out)
{
    __shared__ __align__(16) float4 sM4[128 * 9];   // 18 KB padded rows
    __shared__ __align__(16) u64    sWu2[32 * 32];  // 8 KB [sd][pair]

    const int tid  = threadIdx.x;
    const int head = blockIdx.x & 15;
    const int tok0 = (blockIdx.x >> 4) * 128;
    const int dg   = tid & 7;
    const int tg   = tid >> 3;

    ((float4*)sWu2)[tid]       = ((const float4*)Wu)[tid];
    ((float4*)sWu2)[tid + 256] = ((const float4*)Wu)[tid + 256];

#pragma unroll
    for (int k = 0; k < 4; k++) {
        int idx = k * 256 + tid;
        int tok = idx >> 3, j2 = idx & 7;
        sM4[tok * 9 + j2] = g_mem4[((size_t)(tok0 + tok) * NHEADS + head) * 8 + j2];
    }
    __syncthreads();

    u64 acc[4][4];
    {
        const u64* bu2 = (const u64*)bu;
#pragma unroll
        for (int j = 0; j < 4; j++) {
            u64 b = __ldg(&bu2[dg * 4 + j]);
            acc[0][j] = b; acc[1][j] = b; acc[2][j] = b; acc[3][j] = b;
        }
    }

#pragma unroll
    for (int j2 = 0; j2 < 8; j2++) {    // mem f4 chunk = sd 4j2..4j2+3
        float4 mv[4];
#pragma unroll
        for (int t = 0; t < 4; t++)
            mv[t] = sM4[(tg * 4 + t) * 9 + j2];
#pragma unroll
        for (int ee = 0; ee < 4; ee++) {
            const int sd = j2 * 4 + ee;
            ulonglong2 w01 = *(const ulonglong2*)&sWu2[sd * 32 + dg * 4];
            ulonglong2 w23 = *(const ulonglong2*)&sWu2[sd * 32 + dg * 4 + 2];
            const float* mf0 = (const float*)&mv[0];
            const float* mf1 = (const float*)&mv[1];
            const float* mf2 = (const float*)&mv[2];
            const float* mf3 = (const float*)&mv[3];
            u64 h0 = pack2(mf0[ee], mf0[ee]);
            u64 h1 = pack2(mf1[ee], mf1[ee]);
            u64 h2 = pack2(mf2[ee], mf2[ee]);
            u64 h3 = pack2(mf3[ee], mf3[ee]);
            fma2(acc[0][0], h0, w01.x); fma2(acc[0][1], h0, w01.y);
            fma2(acc[0][2], h0, w23.x); fma2(acc[0][3], h0, w23.y);
            fma2(acc[1][0], h1, w01.x); fma2(acc[1][1], h1, w01.y);
            fma2(acc[1][2], h1, w23.x); fma2(acc[1][3], h1, w23.y);
            fma2(acc[2][0], h2, w01.x); fma2(acc[2][1], h2, w01.y);
            fma2(acc[2][2], h2, w23.x); fma2(acc[2][3], h2, w23.y);
            fma2(acc[3][0], h3, w01.x); fma2(acc[3][1], h3, w01.y);
            fma2(acc[3][2], h3, w23.x); fma2(acc[3][3], h3, w23.y);
        }
    }

    const float rw = __ldg(&res_w[0]);
#pragma unroll
    for (int t = 0; t < 4; t++) {
        const int token = tok0 + tg * 4 + t;
        const size_t base = (size_t)token * 256 + head * 16 + dg * 2;
        const float4* hid4 = (const float4*)hidden + base;
        float4* out4 = (float4*)out + base;
        float2 aa = unpack2(acc[t][0]);
        float2 ab = unpack2(acc[t][1]);
        float2 ac = unpack2(acc[t][2]);
        float2 ad = unpack2(acc[t][3]);
        float4 h0 = __ldcs(&hid4[0]);
        float4 h1 = __ldcs(&hid4[1]);
        float4 o0, o1;
        o0.x = fmaf(aa.x, rw, h0.x); o0.y = fmaf(aa.y, rw, h0.y);
        o0.z = fmaf(ab.x, rw, h0.z); o0.w = fmaf(ab.y, rw, h0.w);
        o1.x = fmaf(ac.x, rw, h1.x); o1.y = fmaf(ac.y, rw, h1.y);
        o1.z = fmaf(ad.x, rw, h1.z); o1.w = fmaf(ad.y, rw, h1.w);
        __stcs(&out4[0], o0);
        __stcs(&out4[1], o1);
    }
}

// ---------------------------------------------------------------------------
extern "C" void kernel_launch(void* const* d_in, const int* in_sizes, int n_in,
                              void* d_out, int out_size)
{
    const float* hidden = (const float*)d_in[0];
    const float* stack  = (const float*)d_in[1];
    const float* mask   = (const float*)d_in[2];
    const float* Wa     = (const float*)d_in[3];
    const float* ba     = (const float*)d_in[4];
    const float* Wd     = (const float*)d_in[5];
    const float* bd     = (const float*)d_in[6];
    const float* Wu     = (const float*)d_in[7];
    const float* bu     = (const float*)d_in[8];
    const float* Wg     = (const float*)d_in[9];
    const float* bg     = (const float*)d_in[10];
    const float* res_w  = (const float*)d_in[11];

    float* out       = (float*)d_out;
    float* new_stack = out + (size_t)N_TOKENS * HDIM;
    float* new_mask  = new_stack + (size_t)N_TOKENS * NHEADS * SLOTS * SD;

    (void)in_sizes; (void)n_in; (void)out_size;

    k_waT<<<192, 256>>>(Wa);
    k_actions_part<<<256, 256>>>(hidden);
    k_act_reduce<<<N_TOKENS / 16, 256>>>(ba);
    k_kv<<<(N_TOKENS / 128) * NHEADS, 256>>>(hidden, Wd, bd);
    k_stack<<<N_TOKENS * NHEADS / 8, 256>>>(stack, mask, Wg, bg,
                                            new_stack, new_mask);
    k_out<<<(N_TOKENS / 128) * NHEADS, 256>>>(hidden, Wu, bu, res_w, out);
}

// round 10
// speedup vs baseline: 1.1494x; 1.0110x over previous
#include <cuda_runtime.h>
#include <cstdint>
#include <cstddef>

#define N_TOKENS 8192
#define HDIM     1024
#define NHEADS   16
#define SLOTS    16
#define SD       32
#define HD       64
#define FULLMASK 0xffffffffu

typedef unsigned long long u64;

__device__ float4 g_act4[N_TOKENS * NHEADS];
__device__ float  g_WaT[48 * HDIM];                      // WaT[col][k]
__device__ float  g_part[4 * N_TOKENS * 48];             // k-split partials
__device__ float4 g_kv4[(size_t)N_TOKENS * NHEADS * 8];  // kv [tok][head][32]
__device__ float4 g_mem4[(size_t)N_TOKENS * NHEADS * 8]; // mem [tok][head][32]

// ---------------------- helpers ----------------------
__device__ __forceinline__ u64 pack2(float x, float y) {
    u64 r; asm("mov.b64 %0,{%1,%2};" : "=l"(r) : "f"(x), "f"(y)); return r;
}
__device__ __forceinline__ void fma2(u64& d, u64 a, u64 b) {
    asm("fma.rn.f32x2 %0,%1,%2,%0;" : "+l"(d) : "l"(a), "l"(b));
}
__device__ __forceinline__ float2 unpack2(u64 v) {
    float2 r; asm("mov.b64 {%0,%1},%2;" : "=f"(r.x), "=f"(r.y) : "l"(v)); return r;
}
__device__ __forceinline__ float4 f4zero() { return make_float4(0.f, 0.f, 0.f, 0.f); }
__device__ __forceinline__ float4 f4fma(float a, float4 b, float4 c) {
    return make_float4(fmaf(a, b.x, c.x), fmaf(a, b.y, c.y),
                       fmaf(a, b.z, c.z), fmaf(a, b.w, c.w));
}
__device__ __forceinline__ float4 f4add(float4 a, float4 b) {
    return make_float4(a.x + b.x, a.y + b.y, a.z + b.z, a.w + b.w);
}
__device__ __forceinline__ float dot4(float4 a, float4 b) {
    return fmaf(a.x, b.x, fmaf(a.y, b.y, fmaf(a.z, b.z, a.w * b.w)));
}
__device__ __forceinline__ float4 f4shflxor(float4 v, int m) {
    return make_float4(__shfl_xor_sync(FULLMASK, v.x, m),
                       __shfl_xor_sync(FULLMASK, v.y, m),
                       __shfl_xor_sync(FULLMASK, v.z, m),
                       __shfl_xor_sync(FULLMASK, v.w, m));
}

// ---------------------------------------------------------------------------
// Kernel 0: transpose Wa [1024][48] -> g_WaT [48][1024]
// ---------------------------------------------------------------------------
__global__ __launch_bounds__(256) void k_waT(const float* __restrict__ Wa)
{
    const int col = blockIdx.x >> 2;
    const int k   = (blockIdx.x & 3) * 256 + threadIdx.x;
    g_WaT[col * HDIM + k] = Wa[(size_t)k * 48 + col];
}

// ---------------------------------------------------------------------------
// Kernel 1a: partial logits GEMM. Block = 128 tok x 48 col x 256-k chunk.
// ---------------------------------------------------------------------------
__global__ __launch_bounds__(256) void k_actions_part(
    const float* __restrict__ hidden)
{
    __shared__ __align__(16) float sA[128][68];
    __shared__ __align__(16) float sWT[48][68];

    const int tid  = threadIdx.x;
    const int ty   = tid >> 3;
    const int tx   = tid & 7;
    const int tile = blockIdx.x >> 2;
    const int kc   = blockIdx.x & 3;
    const int tok0 = tile * 128;
    const float4* hid4 = (const float4*)hidden;
    const float4* waT4 = (const float4*)g_WaT;

    u64 acc[4][6];
#pragma unroll
    for (int t = 0; t < 4; t++)
#pragma unroll
        for (int j = 0; j < 6; j++) acc[t][j] = 0ull;

#pragma unroll
    for (int sub = 0; sub < 4; sub++) {
        const int k4 = kc * 64 + sub * 16;
#pragma unroll
        for (int idx = tid; idx < 2048; idx += 256) {
            int r = idx >> 4, c4 = idx & 15;
            *(float4*)&sA[r][c4 * 4] = hid4[(size_t)(tok0 + r) * 256 + k4 + c4];
        }
#pragma unroll
        for (int idx = tid; idx < 768; idx += 256) {
            int r = idx >> 4, c4 = idx & 15;
            *(float4*)&sWT[r][c4 * 4] = waT4[(size_t)r * 256 + k4 + c4];
        }
        __syncthreads();

#pragma unroll 8
        for (int k2 = 0; k2 < 32; k2++) {
            u64 a[4];
#pragma unroll
            for (int t = 0; t < 4; t++)
                a[t] = *(const u64*)&sA[ty * 4 + t][k2 * 2];
#pragma unroll
            for (int j = 0; j < 6; j++) {
                u64 w = *(const u64*)&sWT[tx * 6 + j][k2 * 2];
                fma2(acc[0][j], a[0], w);
                fma2(acc[1][j], a[1], w);
                fma2(acc[2][j], a[2], w);
                fma2(acc[3][j], a[3], w);
            }
        }
        __syncthreads();
    }

#pragma unroll
    for (int t = 0; t < 4; t++) {
        const size_t base = ((size_t)kc * N_TOKENS + tok0 + ty * 4 + t) * 48 + tx * 6;
#pragma unroll
        for (int j2 = 0; j2 < 3; j2++) {
            float2 pa = unpack2(acc[t][j2 * 2]);
            float2 pb = unpack2(acc[t][j2 * 2 + 1]);
            *(float2*)&g_part[base + j2 * 2] = make_float2(pa.x + pa.y, pb.x + pb.y);
        }
    }
}

// ---------------------------------------------------------------------------
// Kernel 1b: reduce partials + softmax_3 -> g_act4.
// ---------------------------------------------------------------------------
__global__ __launch_bounds__(256) void k_act_reduce(const float* __restrict__ ba)
{
    const int tid   = threadIdx.x;
    const int head  = tid & 15;
    const int token = blockIdx.x * 16 + (tid >> 4);

    float l[3];
#pragma unroll
    for (int j = 0; j < 3; j++) {
        const size_t col = (size_t)token * 48 + head * 3 + j;
        float s = g_part[col]
                + g_part[(size_t)N_TOKENS * 48 + col]
                + g_part[(size_t)2 * N_TOKENS * 48 + col]
                + g_part[(size_t)3 * N_TOKENS * 48 + col];
        l[j] = (s + __ldg(&ba[head * 3 + j])) * 0.125f;
    }
    float mx = fmaxf(l[0], fmaxf(l[1], l[2]));
    float e0 = __expf(l[0] - mx);
    float e1 = __expf(l[1] - mx);
    float e2 = __expf(l[2] - mx);
    float inv = 1.f / (e0 + e1 + e2);
    g_act4[(size_t)token * NHEADS + head] = make_float4(e0 * inv, e1 * inv, e2 * inv, 0.f);
}

// ---------------------------------------------------------------------------
// Kernel 2: kv = hidden-slice @ Wd + bd. Block = 128 tok x 1 head, 256 thr.
// ---------------------------------------------------------------------------
__global__ __launch_bounds__(256) void k_kv(
    const float* __restrict__ hidden,
    const float* __restrict__ Wd,
    const float* __restrict__ bd)
{
    __shared__ __align__(16) float sAT[64 * 128];   // 32 KB
    __shared__ __align__(16) u64   sWd2[64 * 16];   // 8 KB [d][pair]

    const int tid  = threadIdx.x;
    const int head = blockIdx.x & 15;
    const int tok0 = (blockIdx.x >> 4) * 128;
    const int jg   = tid & 7;
    const int tg   = tid >> 3;

    ((float4*)sWd2)[tid]       = ((const float4*)Wd)[tid];
    ((float4*)sWd2)[tid + 256] = ((const float4*)Wd)[tid + 256];

    const float4* hid4 = (const float4*)hidden;
#pragma unroll
    for (int k = 0; k < 8; k++) {
        int idx = k * 256 + tid;
        int tok = idx >> 4, c4 = idx & 15;
        float4 v = __ldcs(&hid4[(size_t)(tok0 + tok) * 256 + head * 16 + c4]);
        int d0 = c4 * 4;
        const int tq = tok >> 2, tr = tok & 3;
        sAT[(d0 + 0) * 128 + ((tq ^ ((d0 + 0) & 31)) << 2) + tr] = v.x;
        sAT[(d0 + 1) * 128 + ((tq ^ ((d0 + 1) & 31)) << 2) + tr] = v.y;
        sAT[(d0 + 2) * 128 + ((tq ^ ((d0 + 2) & 31)) << 2) + tr] = v.z;
        sAT[(d0 + 3) * 128 + ((tq ^ ((d0 + 3) & 31)) << 2) + tr] = v.w;
    }
    __syncthreads();

    u64 acc[4][2];
    {
        const u64* bd2 = (const u64*)bd;
        u64 b0 = __ldg(&bd2[jg * 2]);
        u64 b1 = __ldg(&bd2[jg * 2 + 1]);
#pragma unroll
        for (int t = 0; t < 4; t++) { acc[t][0] = b0; acc[t][1] = b1; }
    }

#pragma unroll 16
    for (int d = 0; d < HD; d++) {
        float4 a4 = *(const float4*)&sAT[d * 128 + ((tg ^ (d & 31)) << 2)];
        const u64* wp = &sWd2[d * 16 + jg * 2];
        u64 w0 = wp[0], w1 = wp[1];
        u64 h0 = pack2(a4.x, a4.x), h1 = pack2(a4.y, a4.y);
        u64 h2 = pack2(a4.z, a4.z), h3 = pack2(a4.w, a4.w);
        fma2(acc[0][0], h0, w0); fma2(acc[0][1], h0, w1);
        fma2(acc[1][0], h1, w0); fma2(acc[1][1], h1, w1);
        fma2(acc[2][0], h2, w0); fma2(acc[2][1], h2, w1);
        fma2(acc[3][0], h3, w0); fma2(acc[3][1], h3, w1);
    }

    float4* kvout = g_kv4 + ((size_t)(tok0 + tg * 4) * NHEADS + head) * 8 + jg;
#pragma unroll
    for (int t = 0; t < 4; t++) {
        float2 lo = unpack2(acc[t][0]);
        float2 hi = unpack2(acc[t][1]);
        kvout[t * 128] = make_float4(lo.x, lo.y, hi.x, hi.y);
    }
}

// ---------------------------------------------------------------------------
// Kernel 3: stack update + gate softmax + mem. Warp = (token, head).
// (R6 version: direct mask LDGs, occupancy hint 3.)
// ---------------------------------------------------------------------------
__global__ __launch_bounds__(256, 3) void k_stack(
    const float* __restrict__ stack,
    const float* __restrict__ mask,
    const float* __restrict__ Wg,
    const float* __restrict__ bg,
    float* __restrict__ new_stack,
    float* __restrict__ new_mask)
{
    const int tid  = threadIdx.x;
    const int wl   = tid >> 5;
    const int lane = tid & 31;
    const int g    = lane >> 3;
    const int c    = lane & 7;

    const size_t th = (size_t)blockIdx.x * 8 + wl;
    const float4* stk4 = (const float4*)stack + th * 128;

    float4 st[4];
#pragma unroll
    for (int i = 0; i < 4; i++) st[i] = __ldcs(&stk4[i * 32 + lane]);

    const float4 kv4 = __ldg(&g_kv4[th * 8 + c]);
    const float4 act = __ldg(&g_act4[th]);
    const float a_push = act.x, a_pop = act.y, a_noop = act.z;
    const float4 wg4 = __ldg(&((const float4*)Wg)[c]);

    float q[4];
#pragma unroll
    for (int i = 0; i < 4; i++) {
        q[i] = dot4(st[i], wg4);
        q[i] += __shfl_xor_sync(FULLMASK, q[i], 1);
        q[i] += __shfl_xor_sync(FULLMASK, q[i], 2);
        q[i] += __shfl_xor_sync(FULLMASK, q[i], 4);
    }
    float qk = dot4(kv4, wg4);
    qk += __shfl_xor_sync(FULLMASK, qk, 1);
    qk += __shfl_xor_sync(FULLMASK, qk, 2);
    qk += __shfl_xor_sync(FULLMASK, qk, 4);

    float qn[4], qp[4];
#pragma unroll
    for (int i = 0; i < 4; i++) {
        float sn = (g == 0) ? ((i < 3) ? q[i + 1] : 0.f) : q[i];
        qn[i] = __shfl_sync(FULLMASK, sn, (lane + 8) & 31);
        float sp = (g == 3) ? ((i > 0) ? q[i - 1] : 0.f) : q[i];
        qp[i] = __shfl_sync(FULLMASK, sp, (lane + 24) & 31);
    }
    if (g == 0) qp[0] = qk;

    const float bgv = __ldg(&bg[0]);
    const float* mk = mask + th * SLOTS;
    float nm[4], e[4];
    float mx = -3.4e38f;
#pragma unroll
    for (int i = 0; i < 4; i++) {
        const int slot = i * 4 + g;
        float m  = __ldcs(&mk[slot]);
        float mn = (slot < 15) ? __ldcs(&mk[slot + 1]) : 0.f;
        float mp = (slot > 0)  ? __ldcs(&mk[slot - 1]) : 1.f;
        nm[i] = fmaf(a_push, mp, fmaf(a_pop, mn, a_noop * m));
        float sc = fmaf(a_push, qp[i], fmaf(a_pop, qn[i], a_noop * q[i])) + bgv;
        sc += (1.f - nm[i]) * (-1e9f);
        e[i] = sc;
        mx = fmaxf(mx, sc);
    }
    mx = fmaxf(mx, __shfl_xor_sync(FULLMASK, mx, 8));
    mx = fmaxf(mx, __shfl_xor_sync(FULLMASK, mx, 16));
    float ssum = 0.f;
#pragma unroll
    for (int i = 0; i < 4; i++) { e[i] = __expf(e[i] - mx); ssum += e[i]; }
    ssum += __shfl_xor_sync(FULLMASK, ssum, 8);
    ssum += __shfl_xor_sync(FULLMASK, ssum, 16);
    const float ginv = 1.f / ssum;

    if (c == 0) {
#pragma unroll
        for (int i = 0; i < 4; i++)
            __stcs(&new_mask[th * SLOTS + i * 4 + g], nm[i]);
    }

    float4* nst4 = (float4*)new_stack + th * 128;
    float4 acc = f4zero();
#pragma unroll
    for (int i = 0; i < 4; i++) {
        const int slot = i * 4 + g;
        float4 nx = (slot < 15) ? __ldcs(&stk4[i * 32 + lane + 8]) : f4zero();
        float4 pv = (slot > 0)  ? __ldcs(&stk4[i * 32 + lane - 8]) : kv4;
        float4 ns;
        ns.x = fmaf(a_push, pv.x, fmaf(a_pop, nx.x, a_noop * st[i].x));
        ns.y = fmaf(a_push, pv.y, fmaf(a_pop, nx.y, a_noop * st[i].y));
        ns.z = fmaf(a_push, pv.z, fmaf(a_pop, nx.z, a_noop * st[i].z));
        ns.w = fmaf(a_push, pv.w, fmaf(a_pop, nx.w, a_noop * st[i].w));
        __stcs(&nst4[i * 32 + lane], ns);
        acc = f4fma(e[i] * ginv, ns, acc);
    }
    acc = f4add(acc, f4shflxor(acc, 8));
    acc = f4add(acc, f4shflxor(acc, 16));
    if (g == 0)
        g_mem4[th * 8 + c] = acc;
}

// ---------------------------------------------------------------------------
// Kernel 4: out = (mem @ Wu + bu)*rw + hidden. Block = 128 tok x 1 head.
// Conflict-free: thread (tg = tid>>3, dg = tid&7) owns tokens {tg+32t} and
// d-pairs 4dg..4dg+3. mem rows stride 9 f4 -> read banks 4*tg%32 distinct.
// Wu split: A = pairs (4dg,4dg+1), B = (4dg+2,4dg+3) -> banks dg*4 distinct.
// ---------------------------------------------------------------------------
__global__ __launch_bounds__(256) void k_out(
    const float* __restrict__ hidden,
    const float* __restrict__ Wu,
    const float* __restrict__ bu,
    const float* __restrict__ res_w,
    float* __restrict__ out)
{
    __shared__ __align__(16) float4 sM4[128 * 9];   // 18 KB
    __shared__ __align__(16) u64    sWuA[32 * 16];  // 4 KB: [sd][dg] f4-of-2-u64
    __shared__ __align__(16) u64    sWuB[32 * 16];  // 4 KB

    const int tid  = threadIdx.x;
    const int head = blockIdx.x & 15;
    const int tok0 = (blockIdx.x >> 4) * 128;
    const int dg   = tid & 7;
    const int tg   = tid >> 3;   // 0..31

    // Wu fill: ALL 512 f4 of Wu (fix of R9 bug: two passes, i = k*256+tid).
    // f4 i covers u64 pairs (2q, 2q+1), q = i&15, sd = i>>4.
    // q even -> A[sd][q>>1], q odd -> B[sd][q>>1].
#pragma unroll
    for (int k = 0; k < 2; k++) {
        int i = k * 256 + tid;
        float4 v = ((const float4*)Wu)[i];
        int sd = i >> 4, q = i & 15;
        u64* dst = (q & 1) ? sWuB : sWuA;
        *(float4*)&dst[(sd * 8 + (q >> 1)) * 2] = v;
    }
#pragma unroll
    for (int k = 0; k < 4; k++) {
        int idx = k * 256 + tid;
        int tok = idx >> 3, j2 = idx & 7;
        sM4[tok * 9 + j2] = g_mem4[((size_t)(tok0 + tok) * NHEADS + head) * 8 + j2];
    }
    __syncthreads();

    u64 acc[4][4];
    {
        const u64* bu2 = (const u64*)bu;
#pragma unroll
        for (int j = 0; j < 4; j++) {
            u64 b = __ldg(&bu2[dg * 4 + j]);
            acc[0][j] = b; acc[1][j] = b; acc[2][j] = b; acc[3][j] = b;
        }
    }

#pragma unroll
    for (int j2 = 0; j2 < 8; j2++) {    // mem f4 chunk = sd 4j2..4j2+3
        float4 mv[4];
#pragma unroll
        for (int t = 0; t < 4; t++)
            mv[t] = sM4[(tg + 32 * t) * 9 + j2];
#pragma unroll
        for (int ee = 0; ee < 4; ee++) {
            const int sd = j2 * 4 + ee;
            ulonglong2 wA = *(const ulonglong2*)&sWuA[(sd * 8 + dg) * 2];
            ulonglong2 wB = *(const ulonglong2*)&sWuB[(sd * 8 + dg) * 2];
            const float* mf0 = (const float*)&mv[0];
            const float* mf1 = (const float*)&mv[1];
            const float* mf2 = (const float*)&mv[2];
            const float* mf3 = (const float*)&mv[3];
            u64 h0 = pack2(mf0[ee], mf0[ee]);
            u64 h1 = pack2(mf1[ee], mf1[ee]);
            u64 h2 = pack2(mf2[ee], mf2[ee]);
            u64 h3 = pack2(mf3[ee], mf3[ee]);
            fma2(acc[0][0], h0, wA.x); fma2(acc[0][1], h0, wA.y);
            fma2(acc[0][2], h0, wB.x); fma2(acc[0][3], h0, wB.y);
            fma2(acc[1][0], h1, wA.x); fma2(acc[1][1], h1, wA.y);
            fma2(acc[1][2], h1, wB.x); fma2(acc[1][3], h1, wB.y);
            fma2(acc[2][0], h2, wA.x); fma2(acc[2][1], h2, wA.y);
            fma2(acc[2][2], h2, wB.x); fma2(acc[2][3], h2, wB.y);
            fma2(acc[3][0], h3, wA.x); fma2(acc[3][1], h3, wA.y);
            fma2(acc[3][2], h3, wB.x); fma2(acc[3][3], h3, wB.y);
        }
    }

    const float rw = __ldg(&res_w[0]);
#pragma unroll
    for (int t = 0; t < 4; t++) {
        const int token = tok0 + tg + 32 * t;
        const size_t base = (size_t)token * 256 + head * 16 + dg * 2;
        const float4* hid4 = (const float4*)hidden + base;
        float4* out4 = (float4*)out + base;
        float2 aa = unpack2(acc[t][0]);
        float2 ab = unpack2(acc[t][1]);
        float2 ac = unpack2(acc[t][2]);
        float2 ad = unpack2(acc[t][3]);
        float4 h0 = __ldcs(&hid4[0]);
        float4 h1 = __ldcs(&hid4[1]);
        float4 o0, o1;
        o0.x = fmaf(aa.x, rw, h0.x); o0.y = fmaf(aa.y, rw, h0.y);
        o0.z = fmaf(ab.x, rw, h0.z); o0.w = fmaf(ab.y, rw, h0.w);
        o1.x = fmaf(ac.x, rw, h1.x); o1.y = fmaf(ac.y, rw, h1.y);
        o1.z = fmaf(ad.x, rw, h1.z); o1.w = fmaf(ad.y, rw, h1.w);
        __stcs(&out4[0], o0);
        __stcs(&out4[1], o1);
    }
}

// ---------------------------------------------------------------------------
extern "C" void kernel_launch(void* const* d_in, const int* in_sizes, int n_in,
                              void* d_out, int out_size)
{
    const float* hidden = (const float*)d_in[0];
    const float* stack  = (const float*)d_in[1];
    const float* mask   = (const float*)d_in[2];
    const float* Wa     = (const float*)d_in[3];
    const float* ba     = (const float*)d_in[4];
    const float* Wd     = (const float*)d_in[5];
    const float* bd     = (const float*)d_in[6];
    const float* Wu     = (const float*)d_in[7];
    const float* bu     = (const float*)d_in[8];
    const float* Wg     = (const float*)d_in[9];
    const float* bg     = (const float*)d_in[10];
    const float* res_w  = (const float*)d_in[11];

    float* out       = (float*)d_out;
    float* new_stack = out + (size_t)N_TOKENS * HDIM;
    float* new_mask  = new_stack + (size_t)N_TOKENS * NHEADS * SLOTS * SD;

    (void)in_sizes; (void)n_in; (void)out_size;

    k_waT<<<192, 256>>>(Wa);
    k_actions_part<<<256, 256>>>(hidden);
    k_act_reduce<<<N_TOKENS / 16, 256>>>(ba);
    k_kv<<<(N_TOKENS / 128) * NHEADS, 256>>>(hidden, Wd, bd);
    k_stack<<<N_TOKENS * NHEADS / 8, 256>>>(stack, mask, Wg, bg,
                                            new_stack, new_mask);
    k_out<<<(N_TOKENS / 128) * NHEADS, 256>>>(hidden, Wu, bu, res_w, out);
}

// round 11
// speedup vs baseline: 1.1578x; 1.0073x over previous
#include <cuda_runtime.h>
#include <cstdint>
#include <cstddef>

#define N_TOKENS 8192
#define HDIM     1024
#define NHEADS   16
#define SLOTS    16
#define SD       32
#define HD       64
#define FULLMASK 0xffffffffu

typedef unsigned long long u64;

__device__ float4 g_act4[N_TOKENS * NHEADS];
__device__ float  g_WaT[48 * HDIM];                      // WaT[col][k]
__device__ float  g_part[4 * N_TOKENS * 48];             // k-split partials
__device__ float4 g_kv4[(size_t)N_TOKENS * NHEADS * 8];  // kv [tok][head][32]

// ---------------------- helpers ----------------------
__device__ __forceinline__ u64 pack2(float x, float y) {
    u64 r; asm("mov.b64 %0,{%1,%2};" : "=l"(r) : "f"(x), "f"(y)); return r;
}
__device__ __forceinline__ void fma2(u64& d, u64 a, u64 b) {
    asm("fma.rn.f32x2 %0,%1,%2,%0;" : "+l"(d) : "l"(a), "l"(b));
}
__device__ __forceinline__ float2 unpack2(u64 v) {
    float2 r; asm("mov.b64 {%0,%1},%2;" : "=f"(r.x), "=f"(r.y) : "l"(v)); return r;
}
__device__ __forceinline__ float4 f4zero() { return make_float4(0.f, 0.f, 0.f, 0.f); }
__device__ __forceinline__ float4 f4fma(float a, float4 b, float4 c) {
    return make_float4(fmaf(a, b.x, c.x), fmaf(a, b.y, c.y),
                       fmaf(a, b.z, c.z), fmaf(a, b.w, c.w));
}
__device__ __forceinline__ float4 f4add(float4 a, float4 b) {
    return make_float4(a.x + b.x, a.y + b.y, a.z + b.z, a.w + b.w);
}
__device__ __forceinline__ float dot4(float4 a, float4 b) {
    return fmaf(a.x, b.x, fmaf(a.y, b.y, fmaf(a.z, b.z, a.w * b.w)));
}
__device__ __forceinline__ float4 f4shflxor(float4 v, int m) {
    return make_float4(__shfl_xor_sync(FULLMASK, v.x, m),
                       __shfl_xor_sync(FULLMASK, v.y, m),
                       __shfl_xor_sync(FULLMASK, v.z, m),
                       __shfl_xor_sync(FULLMASK, v.w, m));
}

// ---------------------------------------------------------------------------
// Kernel 0: transpose Wa [1024][48] -> g_WaT [48][1024]
// ---------------------------------------------------------------------------
__global__ __launch_bounds__(256) void k_waT(const float* __restrict__ Wa)
{
    const int col = blockIdx.x >> 2;
    const int k   = (blockIdx.x & 3) * 256 + threadIdx.x;
    g_WaT[col * HDIM + k] = Wa[(size_t)k * 48 + col];
}

// ---------------------------------------------------------------------------
// Kernel 1a: partial logits GEMM. Block = 128 tok x 48 col x 256-k chunk.
// ---------------------------------------------------------------------------
__global__ __launch_bounds__(256) void k_actions_part(
    const float* __restrict__ hidden)
{
    __shared__ __align__(16) float sA[128][68];
    __shared__ __align__(16) float sWT[48][68];

    const int tid  = threadIdx.x;
    const int ty   = tid >> 3;
    const int tx   = tid & 7;
    const int tile = blockIdx.x >> 2;
    const int kc   = blockIdx.x & 3;
    const int tok0 = tile * 128;
    const float4* hid4 = (const float4*)hidden;
    const float4* waT4 = (const float4*)g_WaT;

    u64 acc[4][6];
#pragma unroll
    for (int t = 0; t < 4; t++)
#pragma unroll
        for (int j = 0; j < 6; j++) acc[t][j] = 0ull;

#pragma unroll
    for (int sub = 0; sub < 4; sub++) {
        const int k4 = kc * 64 + sub * 16;
#pragma unroll
        for (int idx = tid; idx < 2048; idx += 256) {
            int r = idx >> 4, c4 = idx & 15;
            *(float4*)&sA[r][c4 * 4] = hid4[(size_t)(tok0 + r) * 256 + k4 + c4];
        }
#pragma unroll
        for (int idx = tid; idx < 768; idx += 256) {
            int r = idx >> 4, c4 = idx & 15;
            *(float4*)&sWT[r][c4 * 4] = waT4[(size_t)r * 256 + k4 + c4];
        }
        __syncthreads();

#pragma unroll 8
        for (int k2 = 0; k2 < 32; k2++) {
            u64 a[4];
#pragma unroll
            for (int t = 0; t < 4; t++)
                a[t] = *(const u64*)&sA[ty * 4 + t][k2 * 2];
#pragma unroll
            for (int j = 0; j < 6; j++) {
                u64 w = *(const u64*)&sWT[tx * 6 + j][k2 * 2];
                fma2(acc[0][j], a[0], w);
                fma2(acc[1][j], a[1], w);
                fma2(acc[2][j], a[2], w);
                fma2(acc[3][j], a[3], w);
            }
        }
        __syncthreads();
    }

#pragma unroll
    for (int t = 0; t < 4; t++) {
        const size_t base = ((size_t)kc * N_TOKENS + tok0 + ty * 4 + t) * 48 + tx * 6;
#pragma unroll
        for (int j2 = 0; j2 < 3; j2++) {
            float2 pa = unpack2(acc[t][j2 * 2]);
            float2 pb = unpack2(acc[t][j2 * 2 + 1]);
            *(float2*)&g_part[base + j2 * 2] = make_float2(pa.x + pa.y, pb.x + pb.y);
        }
    }
}

// ---------------------------------------------------------------------------
// Kernel 1b: reduce partials + softmax_3 -> g_act4.
// ---------------------------------------------------------------------------
__global__ __launch_bounds__(256) void k_act_reduce(const float* __restrict__ ba)
{
    const int tid   = threadIdx.x;
    const int head  = tid & 15;
    const int token = blockIdx.x * 16 + (tid >> 4);

    float l[3];
#pragma unroll
    for (int j = 0; j < 3; j++) {
        const size_t col = (size_t)token * 48 + head * 3 + j;
        float s = g_part[col]
                + g_part[(size_t)N_TOKENS * 48 + col]
                + g_part[(size_t)2 * N_TOKENS * 48 + col]
                + g_part[(size_t)3 * N_TOKENS * 48 + col];
        l[j] = (s + __ldg(&ba[head * 3 + j])) * 0.125f;
    }
    float mx = fmaxf(l[0], fmaxf(l[1], l[2]));
    float e0 = __expf(l[0] - mx);
    float e1 = __expf(l[1] - mx);
    float e2 = __expf(l[2] - mx);
    float inv = 1.f / (e0 + e1 + e2);
    g_act4[(size_t)token * NHEADS + head] = make_float4(e0 * inv, e1 * inv, e2 * inv, 0.f);
}

// ---------------------------------------------------------------------------
// Kernel 2: kv = hidden-slice @ Wd + bd. Block = 128 tok x 1 head, 256 thr.
// ---------------------------------------------------------------------------
__global__ __launch_bounds__(256) void k_kv(
    const float* __restrict__ hidden,
    const float* __restrict__ Wd,
    const float* __restrict__ bd)
{
    __shared__ __align__(16) float sAT[64 * 128];   // 32 KB
    __shared__ __align__(16) u64   sWd2[64 * 16];   // 8 KB [d][pair]

    const int tid  = threadIdx.x;
    const int head = blockIdx.x & 15;
    const int tok0 = (blockIdx.x >> 4) * 128;
    const int jg   = tid & 7;
    const int tg   = tid >> 3;

    ((float4*)sWd2)[tid]       = ((const float4*)Wd)[tid];
    ((float4*)sWd2)[tid + 256] = ((const float4*)Wd)[tid + 256];

    const float4* hid4 = (const float4*)hidden;
#pragma unroll
    for (int k = 0; k < 8; k++) {
        int idx = k * 256 + tid;
        int tok = idx >> 4, c4 = idx & 15;
        float4 v = __ldcs(&hid4[(size_t)(tok0 + tok) * 256 + head * 16 + c4]);
        int d0 = c4 * 4;
        const int tq = tok >> 2, tr = tok & 3;
        sAT[(d0 + 0) * 128 + ((tq ^ ((d0 + 0) & 31)) << 2) + tr] = v.x;
        sAT[(d0 + 1) * 128 + ((tq ^ ((d0 + 1) & 31)) << 2) + tr] = v.y;
        sAT[(d0 + 2) * 128 + ((tq ^ ((d0 + 2) & 31)) << 2) + tr] = v.z;
        sAT[(d0 + 3) * 128 + ((tq ^ ((d0 + 3) & 31)) << 2) + tr] = v.w;
    }
    __syncthreads();

    u64 acc[4][2];
    {
        const u64* bd2 = (const u64*)bd;
        u64 b0 = __ldg(&bd2[jg * 2]);
        u64 b1 = __ldg(&bd2[jg * 2 + 1]);
#pragma unroll
        for (int t = 0; t < 4; t++) { acc[t][0] = b0; acc[t][1] = b1; }
    }

#pragma unroll 16
    for (int d = 0; d < HD; d++) {
        float4 a4 = *(const float4*)&sAT[d * 128 + ((tg ^ (d & 31)) << 2)];
        const u64* wp = &sWd2[d * 16 + jg * 2];
        u64 w0 = wp[0], w1 = wp[1];
        u64 h0 = pack2(a4.x, a4.x), h1 = pack2(a4.y, a4.y);
        u64 h2 = pack2(a4.z, a4.z), h3 = pack2(a4.w, a4.w);
        fma2(acc[0][0], h0, w0); fma2(acc[0][1], h0, w1);
        fma2(acc[1][0], h1, w0); fma2(acc[1][1], h1, w1);
        fma2(acc[2][0], h2, w0); fma2(acc[2][1], h2, w1);
        fma2(acc[3][0], h3, w0); fma2(acc[3][1], h3, w1);
    }

    float4* kvout = g_kv4 + ((size_t)(tok0 + tg * 4) * NHEADS + head) * 8 + jg;
#pragma unroll
    for (int t = 0; t < 4; t++) {
        float2 lo = unpack2(acc[t][0]);
        float2 hi = unpack2(acc[t][1]);
        kvout[t * 128] = make_float4(lo.x, lo.y, hi.x, hi.y);
    }
}

// ---------------------------------------------------------------------------
// Kernel 3 (FUSED): stack update + gate softmax + mem + up-projection + out.
// Warp = (token, head); 8 warps/block. Wu resident in block smem (8 KB).
// After mem reduce, each lane computes out d-pair = lane via 32 CF LDS.64.
// ---------------------------------------------------------------------------
__global__ __launch_bounds__(256, 3) void k_stack_out(
    const float* __restrict__ hidden,
    const float* __restrict__ stack,
    const float* __restrict__ mask,
    const float* __restrict__ Wg,
    const float* __restrict__ bg,
    const float* __restrict__ Wu,
    const float* __restrict__ bu,
    const float* __restrict__ res_w,
    float* __restrict__ out,
    float* __restrict__ new_stack,
    float* __restrict__ new_mask)
{
    __shared__ __align__(16) u64    sWu2[32 * 32];  // 8 KB: Wu natural [sd][pair]
    __shared__ __align__(16) float4 sMem[8][8];     // 512 B: per-warp mem (32 f)

    const int tid  = threadIdx.x;
    const int wl   = tid >> 5;
    const int lane = tid & 31;
    const int g    = lane >> 3;
    const int c    = lane & 7;

    ((float4*)sWu2)[tid]       = ((const float4*)Wu)[tid];
    ((float4*)sWu2)[tid + 256] = ((const float4*)Wu)[tid + 256];
    __syncthreads();

    const size_t th = (size_t)blockIdx.x * 8 + wl;
    const float4* stk4 = (const float4*)stack + th * 128;

    float4 st[4];
#pragma unroll
    for (int i = 0; i < 4; i++) st[i] = __ldcs(&stk4[i * 32 + lane]);

    const float4 kv4 = __ldg(&g_kv4[th * 8 + c]);
    const float4 act = __ldg(&g_act4[th]);
    const float a_push = act.x, a_pop = act.y, a_noop = act.z;
    const float4 wg4 = __ldg(&((const float4*)Wg)[c]);

    float q[4];
#pragma unroll
    for (int i = 0; i < 4; i++) {
        q[i] = dot4(st[i], wg4);
        q[i] += __shfl_xor_sync(FULLMASK, q[i], 1);
        q[i] += __shfl_xor_sync(FULLMASK, q[i], 2);
        q[i] += __shfl_xor_sync(FULLMASK, q[i], 4);
    }
    float qk = dot4(kv4, wg4);
    qk += __shfl_xor_sync(FULLMASK, qk, 1);
    qk += __shfl_xor_sync(FULLMASK, qk, 2);
    qk += __shfl_xor_sync(FULLMASK, qk, 4);

    float qn[4], qp[4];
#pragma unroll
    for (int i = 0; i < 4; i++) {
        float sn = (g == 0) ? ((i < 3) ? q[i + 1] : 0.f) : q[i];
        qn[i] = __shfl_sync(FULLMASK, sn, (lane + 8) & 31);
        float sp = (g == 3) ? ((i > 0) ? q[i - 1] : 0.f) : q[i];
        qp[i] = __shfl_sync(FULLMASK, sp, (lane + 24) & 31);
    }
    if (g == 0) qp[0] = qk;

    const float bgv = __ldg(&bg[0]);
    const float* mk = mask + th * SLOTS;
    float nm[4], e[4];
    float mx = -3.4e38f;
#pragma unroll
    for (int i = 0; i < 4; i++) {
        const int slot = i * 4 + g;
        float m  = __ldcs(&mk[slot]);
        float mn = (slot < 15) ? __ldcs(&mk[slot + 1]) : 0.f;
        float mp = (slot > 0)  ? __ldcs(&mk[slot - 1]) : 1.f;
        nm[i] = fmaf(a_push, mp, fmaf(a_pop, mn, a_noop * m));
        float sc = fmaf(a_push, qp[i], fmaf(a_pop, qn[i], a_noop * q[i])) + bgv;
        sc += (1.f - nm[i]) * (-1e9f);
        e[i] = sc;
        mx = fmaxf(mx, sc);
    }
    mx = fmaxf(mx, __shfl_xor_sync(FULLMASK, mx, 8));
    mx = fmaxf(mx, __shfl_xor_sync(FULLMASK, mx, 16));
    float ssum = 0.f;
#pragma unroll
    for (int i = 0; i < 4; i++) { e[i] = __expf(e[i] - mx); ssum += e[i]; }
    ssum += __shfl_xor_sync(FULLMASK, ssum, 8);
    ssum += __shfl_xor_sync(FULLMASK, ssum, 16);
    const float ginv = 1.f / ssum;

    if (c == 0) {
#pragma unroll
        for (int i = 0; i < 4; i++)
            __stcs(&new_mask[th * SLOTS + i * 4 + g], nm[i]);
    }

    float4* nst4 = (float4*)new_stack + th * 128;
    float4 acc = f4zero();
#pragma unroll
    for (int i = 0; i < 4; i++) {
        const int slot = i * 4 + g;
        float4 nx = (slot < 15) ? __ldcs(&stk4[i * 32 + lane + 8]) : f4zero();
        float4 pv = (slot > 0)  ? __ldcs(&stk4[i * 32 + lane - 8]) : kv4;
        float4 ns;
        ns.x = fmaf(a_push, pv.x, fmaf(a_pop, nx.x, a_noop * st[i].x));
        ns.y = fmaf(a_push, pv.y, fmaf(a_pop, nx.y, a_noop * st[i].y));
        ns.z = fmaf(a_push, pv.z, fmaf(a_pop, nx.z, a_noop * st[i].z));
        ns.w = fmaf(a_push, pv.w, fmaf(a_pop, nx.w, a_noop * st[i].w));
        __stcs(&nst4[i * 32 + lane], ns);
        acc = f4fma(e[i] * ginv, ns, acc);
    }
    acc = f4add(acc, f4shflxor(acc, 8));
    acc = f4add(acc, f4shflxor(acc, 16));
    if (g == 0) sMem[wl][c] = acc;      // mem[4c..4c+3]
    __syncwarp();

    // ---- up-projection: lane owns d-pair = lane (d = 2*lane, 2*lane+1)
    u64 oacc = __ldg(&((const u64*)bu)[lane]);
    const float* memf = (const float*)&sMem[wl][0];
#pragma unroll
    for (int s4 = 0; s4 < 8; s4++) {
        float4 m4 = *(const float4*)&memf[s4 * 4];      // broadcast LDS.128
        u64 w0 = sWu2[(s4 * 4 + 0) * 32 + lane];
        u64 w1 = sWu2[(s4 * 4 + 1) * 32 + lane];
        u64 w2 = sWu2[(s4 * 4 + 2) * 32 + lane];
        u64 w3 = sWu2[(s4 * 4 + 3) * 32 + lane];
        fma2(oacc, pack2(m4.x, m4.x), w0);
        fma2(oacc, pack2(m4.y, m4.y), w1);
        fma2(oacc, pack2(m4.z, m4.z), w2);
        fma2(oacc, pack2(m4.w, m4.w), w3);
    }

    const float rw = __ldg(&res_w[0]);
    const size_t obase = (size_t)(th >> 4) * HDIM + (th & 15) * HD + 2 * lane;
    float2 hv = __ldcs((const float2*)&hidden[obase]);
    float2 ov = unpack2(oacc);
    float2 res;
    res.x = fmaf(ov.x, rw, hv.x);
    res.y = fmaf(ov.y, rw, hv.y);
    __stcs((float2*)&out[obase], res);
}

// ---------------------------------------------------------------------------
extern "C" void kernel_launch(void* const* d_in, const int* in_sizes, int n_in,
                              void* d_out, int out_size)
{
    const float* hidden = (const float*)d_in[0];
    const float* stack  = (const float*)d_in[1];
    const float* mask   = (const float*)d_in[2];
    const float* Wa     = (const float*)d_in[3];
    const float* ba     = (const float*)d_in[4];
    const float* Wd     = (const float*)d_in[5];
    const float* bd     = (const float*)d_in[6];
    const float* Wu     = (const float*)d_in[7];
    const float* bu     = (const float*)d_in[8];
    const float* Wg     = (const float*)d_in[9];
    const float* bg     = (const float*)d_in[10];
    const float* res_w  = (const float*)d_in[11];

    float* out       = (float*)d_out;
    float* new_stack = out + (size_t)N_TOKENS * HDIM;
    float* new_mask  = new_stack + (size_t)N_TOKENS * NHEADS * SLOTS * SD;

    (void)in_sizes; (void)n_in; (void)out_size;

    k_waT<<<192, 256>>>(Wa);
    k_actions_part<<<256, 256>>>(hidden);
    k_act_reduce<<<N_TOKENS / 16, 256>>>(ba);
    k_kv<<<(N_TOKENS / 128) * NHEADS, 256>>>(hidden, Wd, bd);
    k_stack_out<<<N_TOKENS * NHEADS / 8, 256>>>(hidden, stack, mask, Wg, bg,
                                                Wu, bu, res_w,
                                                out, new_stack, new_mask);
}

// round 12
// speedup vs baseline: 1.1854x; 1.0239x over previous
#include <cuda_runtime.h>
#include <cstdint>
#include <cstddef>

#define N_TOKENS 8192
#define HDIM     1024
#define NHEADS   16
#define SLOTS    16
#define SD       32
#define HD       64
#define FULLMASK 0xffffffffu

typedef unsigned long long u64;

__device__ float4 g_act4[N_TOKENS * NHEADS];
__device__ float  g_WaT[48 * HDIM];                      // WaT[col][k]
__device__ float  g_part[4 * N_TOKENS * 48];             // k-split partials
__device__ float4 g_kv4[(size_t)N_TOKENS * NHEADS * 8];  // kv [tok][head][32]

// ---------------------- helpers ----------------------
__device__ __forceinline__ u64 pack2(float x, float y) {
    u64 r; asm("mov.b64 %0,{%1,%2};" : "=l"(r) : "f"(x), "f"(y)); return r;
}
__device__ __forceinline__ void fma2(u64& d, u64 a, u64 b) {
    asm("fma.rn.f32x2 %0,%1,%2,%0;" : "+l"(d) : "l"(a), "l"(b));
}
__device__ __forceinline__ float2 unpack2(u64 v) {
    float2 r; asm("mov.b64 {%0,%1},%2;" : "=f"(r.x), "=f"(r.y) : "l"(v)); return r;
}
__device__ __forceinline__ float4 f4zero() { return make_float4(0.f, 0.f, 0.f, 0.f); }
__device__ __forceinline__ float4 f4fma(float a, float4 b, float4 c) {
    return make_float4(fmaf(a, b.x, c.x), fmaf(a, b.y, c.y),
                       fmaf(a, b.z, c.z), fmaf(a, b.w, c.w));
}
__device__ __forceinline__ float4 f4add(float4 a, float4 b) {
    return make_float4(a.x + b.x, a.y + b.y, a.z + b.z, a.w + b.w);
}
__device__ __forceinline__ float dot4(float4 a, float4 b) {
    return fmaf(a.x, b.x, fmaf(a.y, b.y, fmaf(a.z, b.z, a.w * b.w)));
}
__device__ __forceinline__ float4 f4shflxor(float4 v, int m) {
    return make_float4(__shfl_xor_sync(FULLMASK, v.x, m),
                       __shfl_xor_sync(FULLMASK, v.y, m),
                       __shfl_xor_sync(FULLMASK, v.z, m),
                       __shfl_xor_sync(FULLMASK, v.w, m));
}

// ---------------------------------------------------------------------------
// Kernel 0: transpose Wa [1024][48] -> g_WaT [48][1024]
// ---------------------------------------------------------------------------
__global__ __launch_bounds__(256) void k_waT(const float* __restrict__ Wa)
{
    const int col = blockIdx.x >> 2;
    const int k   = (blockIdx.x & 3) * 256 + threadIdx.x;
    g_WaT[col * HDIM + k] = Wa[(size_t)k * 48 + col];
}

// ---------------------------------------------------------------------------
// Kernel 1: partial logits GEMM. Block = 128 tok x 48 col x 256-k chunk.
// ---------------------------------------------------------------------------
__global__ __launch_bounds__(256) void k_actions_part(
    const float* __restrict__ hidden)
{
    __shared__ __align__(16) float sA[128][68];
    __shared__ __align__(16) float sWT[48][68];

    const int tid  = threadIdx.x;
    const int ty   = tid >> 3;
    const int tx   = tid & 7;
    const int tile = blockIdx.x >> 2;
    const int kc   = blockIdx.x & 3;
    const int tok0 = tile * 128;
    const float4* hid4 = (const float4*)hidden;
    const float4* waT4 = (const float4*)g_WaT;

    u64 acc[4][6];
#pragma unroll
    for (int t = 0; t < 4; t++)
#pragma unroll
        for (int j = 0; j < 6; j++) acc[t][j] = 0ull;

#pragma unroll
    for (int sub = 0; sub < 4; sub++) {
        const int k4 = kc * 64 + sub * 16;
#pragma unroll
        for (int idx = tid; idx < 2048; idx += 256) {
            int r = idx >> 4, c4 = idx & 15;
            *(float4*)&sA[r][c4 * 4] = hid4[(size_t)(tok0 + r) * 256 + k4 + c4];
        }
#pragma unroll
        for (int idx = tid; idx < 768; idx += 256) {
            int r = idx >> 4, c4 = idx & 15;
            *(float4*)&sWT[r][c4 * 4] = waT4[(size_t)r * 256 + k4 + c4];
        }
        __syncthreads();

#pragma unroll 8
        for (int k2 = 0; k2 < 32; k2++) {
            u64 a[4];
#pragma unroll
            for (int t = 0; t < 4; t++)
                a[t] = *(const u64*)&sA[ty * 4 + t][k2 * 2];
#pragma unroll
            for (int j = 0; j < 6; j++) {
                u64 w = *(const u64*)&sWT[tx * 6 + j][k2 * 2];
                fma2(acc[0][j], a[0], w);
                fma2(acc[1][j], a[1], w);
                fma2(acc[2][j], a[2], w);
                fma2(acc[3][j], a[3], w);
            }
        }
        __syncthreads();
    }

#pragma unroll
    for (int t = 0; t < 4; t++) {
        const size_t base = ((size_t)kc * N_TOKENS + tok0 + ty * 4 + t) * 48 + tx * 6;
#pragma unroll
        for (int j2 = 0; j2 < 3; j2++) {
            float2 pa = unpack2(acc[t][j2 * 2]);
            float2 pb = unpack2(acc[t][j2 * 2 + 1]);
            *(float2*)&g_part[base + j2 * 2] = make_float2(pa.x + pa.y, pb.x + pb.y);
        }
    }
}

// ---------------------------------------------------------------------------
// Kernel 2: kv = hidden-slice @ Wd + bd (block = 128 tok x 1 head, 256 thr),
// PLUS absorbed action reduce+softmax for this block's (tokens, head).
// ---------------------------------------------------------------------------
__global__ __launch_bounds__(256) void k_kv(
    const float* __restrict__ hidden,
    const float* __restrict__ Wd,
    const float* __restrict__ bd,
    const float* __restrict__ ba)
{
    __shared__ __align__(16) float sAT[64 * 128];   // 32 KB
    __shared__ __align__(16) u64   sWd2[64 * 16];   // 8 KB [d][pair]

    const int tid  = threadIdx.x;
    const int head = blockIdx.x & 15;
    const int tok0 = (blockIdx.x >> 4) * 128;
    const int jg   = tid & 7;
    const int tg   = tid >> 3;

    ((float4*)sWd2)[tid]       = ((const float4*)Wd)[tid];
    ((float4*)sWd2)[tid + 256] = ((const float4*)Wd)[tid + 256];

    // absorbed action reduce: thread t < 128 handles token tok0+t, this head
    if (tid < 128) {
        const int token = tok0 + tid;
        float l[3];
#pragma unroll
        for (int j = 0; j < 3; j++) {
            const size_t col = (size_t)token * 48 + head * 3 + j;
            float s = g_part[col]
                    + g_part[(size_t)N_TOKENS * 48 + col]
                    + g_part[(size_t)2 * N_TOKENS * 48 + col]
                    + g_part[(size_t)3 * N_TOKENS * 48 + col];
            l[j] = (s + __ldg(&ba[head * 3 + j])) * 0.125f;
        }
        float mx = fmaxf(l[0], fmaxf(l[1], l[2]));
        float e0 = __expf(l[0] - mx);
        float e1 = __expf(l[1] - mx);
        float e2 = __expf(l[2] - mx);
        float inv = 1.f / (e0 + e1 + e2);
        g_act4[(size_t)token * NHEADS + head] =
            make_float4(e0 * inv, e1 * inv, e2 * inv, 0.f);
    }

    const float4* hid4 = (const float4*)hidden;
#pragma unroll
    for (int k = 0; k < 8; k++) {
        int idx = k * 256 + tid;
        int tok = idx >> 4, c4 = idx & 15;
        float4 v = __ldcs(&hid4[(size_t)(tok0 + tok) * 256 + head * 16 + c4]);
        int d0 = c4 * 4;
        const int tq = tok >> 2, tr = tok & 3;
        sAT[(d0 + 0) * 128 + ((tq ^ ((d0 + 0) & 31)) << 2) + tr] = v.x;
        sAT[(d0 + 1) * 128 + ((tq ^ ((d0 + 1) & 31)) << 2) + tr] = v.y;
        sAT[(d0 + 2) * 128 + ((tq ^ ((d0 + 2) & 31)) << 2) + tr] = v.z;
        sAT[(d0 + 3) * 128 + ((tq ^ ((d0 + 3) & 31)) << 2) + tr] = v.w;
    }
    __syncthreads();

    u64 acc[4][2];
    {
        const u64* bd2 = (const u64*)bd;
        u64 b0 = __ldg(&bd2[jg * 2]);
        u64 b1 = __ldg(&bd2[jg * 2 + 1]);
#pragma unroll
        for (int t = 0; t < 4; t++) { acc[t][0] = b0; acc[t][1] = b1; }
    }

#pragma unroll 16
    for (int d = 0; d < HD; d++) {
        float4 a4 = *(const float4*)&sAT[d * 128 + ((tg ^ (d & 31)) << 2)];
        const u64* wp = &sWd2[d * 16 + jg * 2];
        u64 w0 = wp[0], w1 = wp[1];
        u64 h0 = pack2(a4.x, a4.x), h1 = pack2(a4.y, a4.y);
        u64 h2 = pack2(a4.z, a4.z), h3 = pack2(a4.w, a4.w);
        fma2(acc[0][0], h0, w0); fma2(acc[0][1], h0, w1);
        fma2(acc[1][0], h1, w0); fma2(acc[1][1], h1, w1);
        fma2(acc[2][0], h2, w0); fma2(acc[2][1], h2, w1);
        fma2(acc[3][0], h3, w0); fma2(acc[3][1], h3, w1);
    }

    float4* kvout = g_kv4 + ((size_t)(tok0 + tg * 4) * NHEADS + head) * 8 + jg;
#pragma unroll
    for (int t = 0; t < 4; t++) {
        float2 lo = unpack2(acc[t][0]);
        float2 hi = unpack2(acc[t][1]);
        kvout[t * 128] = make_float4(lo.x, lo.y, hi.x, hi.y);
    }
}

// ---------------------------------------------------------------------------
// Kernel 3 (FUSED): stack update + gate softmax + mem + up-projection + out.
// 128-thread blocks (4 warps) for higher occupancy (regs ~72 -> 7 blocks/SM).
// ---------------------------------------------------------------------------
__global__ __launch_bounds__(128, 7) void k_stack_out(
    const float* __restrict__ hidden,
    const float* __restrict__ stack,
    const float* __restrict__ mask,
    const float* __restrict__ Wg,
    const float* __restrict__ bg,
    const float* __restrict__ Wu,
    const float* __restrict__ bu,
    const float* __restrict__ res_w,
    float* __restrict__ out,
    float* __restrict__ new_stack,
    float* __restrict__ new_mask)
{
    __shared__ __align__(16) u64    sWu2[32 * 32];  // 8 KB: Wu natural [sd][pair]
    __shared__ __align__(16) float4 sMem[4][8];

    const int tid  = threadIdx.x;
    const int wl   = tid >> 5;
    const int lane = tid & 31;
    const int g    = lane >> 3;
    const int c    = lane & 7;

#pragma unroll
    for (int k = 0; k < 4; k++)
        ((float4*)sWu2)[k * 128 + tid] = ((const float4*)Wu)[k * 128 + tid];
    __syncthreads();

    const size_t th = (size_t)blockIdx.x * 4 + wl;
    const float4* stk4 = (const float4*)stack + th * 128;

    float4 st[4];
#pragma unroll
    for (int i = 0; i < 4; i++) st[i] = __ldcs(&stk4[i * 32 + lane]);

    const float4 kv4 = __ldg(&g_kv4[th * 8 + c]);
    const float4 act = __ldg(&g_act4[th]);
    const float a_push = act.x, a_pop = act.y, a_noop = act.z;
    const float4 wg4 = __ldg(&((const float4*)Wg)[c]);

    float q[4];
#pragma unroll
    for (int i = 0; i < 4; i++) {
        q[i] = dot4(st[i], wg4);
        q[i] += __shfl_xor_sync(FULLMASK, q[i], 1);
        q[i] += __shfl_xor_sync(FULLMASK, q[i], 2);
        q[i] += __shfl_xor_sync(FULLMASK, q[i], 4);
    }
    float qk = dot4(kv4, wg4);
    qk += __shfl_xor_sync(FULLMASK, qk, 1);
    qk += __shfl_xor_sync(FULLMASK, qk, 2);
    qk += __shfl_xor_sync(FULLMASK, qk, 4);

    float qn[4], qp[4];
#pragma unroll
    for (int i = 0; i < 4; i++) {
        float sn = (g == 0) ? ((i < 3) ? q[i + 1] : 0.f) : q[i];
        qn[i] = __shfl_sync(FULLMASK, sn, (lane + 8) & 31);
        float sp = (g == 3) ? ((i > 0) ? q[i - 1] : 0.f) : q[i];
        qp[i] = __shfl_sync(FULLMASK, sp, (lane + 24) & 31);
    }
    if (g == 0) qp[0] = qk;

    const float bgv = __ldg(&bg[0]);
    const float* mk = mask + th * SLOTS;
    float nm[4], e[4];
    float mx = -3.4e38f;
#pragma unroll
    for (int i = 0; i < 4; i++) {
        const int slot = i * 4 + g;
        float m  = __ldcs(&mk[slot]);
        float mn = (slot < 15) ? __ldcs(&mk[slot + 1]) : 0.f;
        float mp = (slot > 0)  ? __ldcs(&mk[slot - 1]) : 1.f;
        nm[i] = fmaf(a_push, mp, fmaf(a_pop, mn, a_noop * m));
        float sc = fmaf(a_push, qp[i], fmaf(a_pop, qn[i], a_noop * q[i])) + bgv;
        sc += (1.f - nm[i]) * (-1e9f);
        e[i] = sc;
        mx = fmaxf(mx, sc);
    }
    mx = fmaxf(mx, __shfl_xor_sync(FULLMASK, mx, 8));
    mx = fmaxf(mx, __shfl_xor_sync(FULLMASK, mx, 16));
    float ssum = 0.f;
#pragma unroll
    for (int i = 0; i < 4; i++) { e[i] = __expf(e[i] - mx); ssum += e[i]; }
    ssum += __shfl_xor_sync(FULLMASK, ssum, 8);
    ssum += __shfl_xor_sync(FULLMASK, ssum, 16);
    const float ginv = 1.f / ssum;

    if (c == 0) {
#pragma unroll
        for (int i = 0; i < 4; i++)
            __stcs(&new_mask[th * SLOTS + i * 4 + g], nm[i]);
    }

    float4* nst4 = (float4*)new_stack + th * 128;
    float4 acc = f4zero();
#pragma unroll
    for (int i = 0; i < 4; i++) {
        const int slot = i * 4 + g;
        float4 nx = (slot < 15) ? __ldcs(&stk4[i * 32 + lane + 8]) : f4zero();
        float4 pv = (slot > 0)  ? __ldcs(&stk4[i * 32 + lane - 8]) : kv4;
        float4 ns;
        ns.x = fmaf(a_push, pv.x, fmaf(a_pop, nx.x, a_noop * st[i].x));
        ns.y = fmaf(a_push, pv.y, fmaf(a_pop, nx.y, a_noop * st[i].y));
        ns.z = fmaf(a_push, pv.z, fmaf(a_pop, nx.z, a_noop * st[i].z));
        ns.w = fmaf(a_push, pv.w, fmaf(a_pop, nx.w, a_noop * st[i].w));
        __stcs(&nst4[i * 32 + lane], ns);
        acc = f4fma(e[i] * ginv, ns, acc);
    }
    acc = f4add(acc, f4shflxor(acc, 8));
    acc = f4add(acc, f4shflxor(acc, 16));
    if (g == 0) sMem[wl][c] = acc;      // mem[4c..4c+3]
    __syncwarp();

    // ---- up-projection: lane owns d-pair = lane (d = 2*lane, 2*lane+1)
    u64 oacc = __ldg(&((const u64*)bu)[lane]);
    const float* memf = (const float*)&sMem[wl][0];
#pragma unroll
    for (int s4 = 0; s4 < 8; s4++) {
        float4 m4 = *(const float4*)&memf[s4 * 4];      // broadcast LDS.128
        u64 w0 = sWu2[(s4 * 4 + 0) * 32 + lane];
        u64 w1 = sWu2[(s4 * 4 + 1) * 32 + lane];
        u64 w2 = sWu2[(s4 * 4 + 2) * 32 + lane];
        u64 w3 = sWu2[(s4 * 4 + 3) * 32 + lane];
        fma2(oacc, pack2(m4.x, m4.x), w0);
        fma2(oacc, pack2(m4.y, m4.y), w1);
        fma2(oacc, pack2(m4.z, m4.z), w2);
        fma2(oacc, pack2(m4.w, m4.w), w3);
    }

    const float rw = __ldg(&res_w[0]);
    const size_t obase = (size_t)(th >> 4) * HDIM + (th & 15) * HD + 2 * lane;
    float2 hv = __ldcs((const float2*)&hidden[obase]);
    float2 ov = unpack2(oacc);
    float2 res;
    res.x = fmaf(ov.x, rw, hv.x);
    res.y = fmaf(ov.y, rw, hv.y);
    __stcs((float2*)&out[obase], res);
}

// ---------------------------------------------------------------------------
extern "C" void kernel_launch(void* const* d_in, const int* in_sizes, int n_in,
                              void* d_out, int out_size)
{
    const float* hidden = (const float*)d_in[0];
    const float* stack  = (const float*)d_in[1];
    const float* mask   = (const float*)d_in[2];
    const float* Wa     = (const float*)d_in[3];
    const float* ba     = (const float*)d_in[4];
    const float* Wd     = (const float*)d_in[5];
    const float* bd     = (const float*)d_in[6];
    const float* Wu     = (const float*)d_in[7];
    const float* bu     = (const float*)d_in[8];
    const float* Wg     = (const float*)d_in[9];
    const float* bg     = (const float*)d_in[10];
    const float* res_w  = (const float*)d_in[11];

    float* out       = (float*)d_out;
    float* new_stack = out + (size_t)N_TOKENS * HDIM;
    float* new_mask  = new_stack + (size_t)N_TOKENS * NHEADS * SLOTS * SD;

    (void)in_sizes; (void)n_in; (void)out_size;

    k_waT<<<192, 256>>>(Wa);
    k_actions_part<<<256, 256>>>(hidden);
    k_kv<<<(N_TOKENS / 128) * NHEADS, 256>>>(hidden, Wd, bd, ba);
    k_stack_out<<<N_TOKENS * NHEADS / 4, 128>>>(hidden, stack, mask, Wg, bg,
                                                Wu, bu, res_w,
                                                out, new_stack, new_mask);
}